// round 8
// baseline (speedup 1.0000x reference)
#include <cuda_runtime.h>
#include <cuda_bf16.h>
#include <math.h>
#include <stdint.h>

#define E_     8
#define B_     4096
#define D_IN_  1024
#define D_HID_ 2048
#define D_OUT_ 1024
#define G_HID_ 128
#define K_     2

// ==================== helpers ====================
__device__ __forceinline__ void split2(float a, float b, uint32_t& hi, uint32_t& lo) {
    __nv_bfloat16 ha = __float2bfloat16_rn(a), hb = __float2bfloat16_rn(b);
    float ra = a - __bfloat162float(ha);
    float rb = b - __bfloat162float(hb);
    __nv_bfloat16 la = __float2bfloat16_rn(ra), lb = __float2bfloat16_rn(rb);
    hi = (uint32_t)__bfloat16_as_ushort(ha) | ((uint32_t)__bfloat16_as_ushort(hb) << 16);
    lo = (uint32_t)__bfloat16_as_ushort(la) | ((uint32_t)__bfloat16_as_ushort(lb) << 16);
}
__device__ __forceinline__ float bfu(uint32_t u) {
    return __bfloat162float(__ushort_as_bfloat16((unsigned short)(u & 0xffffu)));
}

#define MMA_BF16(c, a0, a1, a2, a3, b0, b1) \
    asm volatile("mma.sync.aligned.m16n8k16.row.col.f32.bf16.bf16.f32 " \
        "{%0,%1,%2,%3},{%4,%5,%6,%7},{%8,%9},{%0,%1,%2,%3};" \
        : "+f"((c)[0]), "+f"((c)[1]), "+f"((c)[2]), "+f"((c)[3]) \
        : "r"(a0), "r"(a1), "r"(a2), "r"(a3), "r"(b0), "r"(b1))

// ==================== device scratch ====================
__device__ int   g_counts[E_];
__device__ int   g_offsets[E_];
__device__ int   g_cursor[E_];
__device__ int   g_tok_e[B_ * K_];
__device__ float g_tok_s[B_ * K_];
__device__ int   g_tok_pos[B_ * K_];
__device__ int   g_pair_token[B_ * K_];
__device__ float g_entropy[B_];
__device__ int   g_mma_ok;
__device__ int   g_badL[3];
__device__ int   g_flags;

__device__ __align__(16) __nv_bfloat16 g_x_hi[(size_t)B_ * D_IN_];
__device__ __align__(16) __nv_bfloat16 g_x_lo[(size_t)B_ * D_IN_];
__device__ __align__(16) __nv_bfloat16 g_w1t_hi[(size_t)E_ * D_HID_ * D_IN_];
__device__ __align__(16) __nv_bfloat16 g_w1t_lo[(size_t)E_ * D_HID_ * D_IN_];
__device__ __align__(16) __nv_bfloat16 g_w2t_hi[(size_t)E_ * D_HID_ * D_HID_];
__device__ __align__(16) __nv_bfloat16 g_w2t_lo[(size_t)E_ * D_HID_ * D_HID_];
__device__ __align__(16) __nv_bfloat16 g_w3t_hi[(size_t)E_ * D_OUT_ * D_HID_];
__device__ __align__(16) __nv_bfloat16 g_w3t_lo[(size_t)E_ * D_OUT_ * D_HID_];
__device__ __align__(16) __nv_bfloat16 g_h1_hi[(size_t)B_ * K_ * D_HID_];
__device__ __align__(16) __nv_bfloat16 g_h1_lo[(size_t)B_ * K_ * D_HID_];
__device__ __align__(16) __nv_bfloat16 g_h2_hi[(size_t)B_ * K_ * D_HID_];
__device__ __align__(16) __nv_bfloat16 g_h2_lo[(size_t)B_ * K_ * D_HID_];
__device__ __align__(16) float g_o_pair[(size_t)B_ * K_ * D_OUT_];

// ==================== small kernels ====================
__global__ void init_kernel() {
    if (threadIdx.x < E_) { g_counts[threadIdx.x] = 0; g_cursor[threadIdx.x] = 0; }
    if (threadIdx.x == 0) {
        g_mma_ok = 0; g_badL[0] = 0; g_badL[1] = 0; g_badL[2] = 0; g_flags = 0;
    }
}

__global__ __launch_bounds__(256)
void zero_h1() {
    size_t i = (size_t)blockIdx.x * 256 + threadIdx.x;
    size_t n = (size_t)B_ * K_ * D_HID_;
    for (; i < n; i += (size_t)gridDim.x * 256) {
        g_h1_hi[i] = __ushort_as_bfloat16(0);
        g_h1_lo[i] = __ushort_as_bfloat16(0);
    }
}

__global__ __launch_bounds__(256)
void prep_x(const float* __restrict__ x) {
    int i = blockIdx.x * 256 + threadIdx.x;
    float v = x[i];
    __nv_bfloat16 h = __float2bfloat16_rn(v);
    g_x_hi[i] = h;
    g_x_lo[i] = __float2bfloat16_rn(v - __bfloat162float(h));
}

__global__ __launch_bounds__(256)
void prep_w(const float* __restrict__ W, __nv_bfloat16* __restrict__ Whi,
            __nv_bfloat16* __restrict__ Wlo, int KD, int ND)
{
    __shared__ float t[32][33];
    const int e = blockIdx.z;
    const float* Wb = W + (size_t)e * KD * ND;
    __nv_bfloat16* Hh = Whi + (size_t)e * KD * ND;
    __nv_bfloat16* Hl = Wlo + (size_t)e * KD * ND;
    const int n0 = blockIdx.x * 32, k0 = blockIdx.y * 32;
    const int tx = threadIdx.x, ty = threadIdx.y;
    #pragma unroll
    for (int i = 0; i < 4; i++) {
        int kl = ty + i * 8;
        t[kl][tx] = Wb[(size_t)(k0 + kl) * ND + n0 + tx];
    }
    __syncthreads();
    #pragma unroll
    for (int i = 0; i < 4; i++) {
        int nl = ty + i * 8;
        float v = t[tx][nl];
        __nv_bfloat16 h = __float2bfloat16_rn(v);
        __nv_bfloat16 l = __float2bfloat16_rn(v - __bfloat162float(h));
        size_t o = (size_t)(n0 + nl) * KD + k0 + tx;
        Hh[o] = h; Hl[o] = l;
    }
}

__global__ __launch_bounds__(128)
void gate_kernel(const float* __restrict__ x,
                 const float* __restrict__ Wg1, const float* __restrict__ bg1,
                 const float* __restrict__ Wg2, const float* __restrict__ bg2,
                 const float* __restrict__ Wg3, const float* __restrict__ bg3,
                 float* __restrict__ out, long long out_sz)
{
    __shared__ __align__(16) float xs[8][D_IN_];
    __shared__ float s_g1[8][G_HID_];
    __shared__ float s_g2[8][G_HID_];
    __shared__ float s_lg[8][E_];

    const int tid = threadIdx.x;
    const int t0  = blockIdx.x * 8;

    const float4* xg  = reinterpret_cast<const float4*>(x + (size_t)t0 * D_IN_);
    float4*       xsv = reinterpret_cast<float4*>(&xs[0][0]);
    #pragma unroll
    for (int i = 0; i < (8 * D_IN_ / 4) / 128; i++)
        xsv[tid + i * 128] = xg[tid + i * 128];
    __syncthreads();

    float acc[8];
    #pragma unroll
    for (int t = 0; t < 8; t++) acc[t] = 0.f;
    for (int i = 0; i < D_IN_; i++) {
        float w = Wg1[i * G_HID_ + tid];
        #pragma unroll
        for (int t = 0; t < 8; t++) acc[t] = fmaf(xs[t][i], w, acc[t]);
    }
    {
        float b = bg1[tid];
        #pragma unroll
        for (int t = 0; t < 8; t++) s_g1[t][tid] = fmaxf(acc[t] + b, 0.f);
    }
    __syncthreads();

    #pragma unroll
    for (int t = 0; t < 8; t++) acc[t] = 0.f;
    for (int i = 0; i < G_HID_; i++) {
        float w = Wg2[i * G_HID_ + tid];
        #pragma unroll
        for (int t = 0; t < 8; t++) acc[t] = fmaf(s_g1[t][i], w, acc[t]);
    }
    {
        float b = bg2[tid];
        #pragma unroll
        for (int t = 0; t < 8; t++) s_g2[t][tid] = fmaxf(acc[t] + b, 0.f);
    }
    __syncthreads();

    if (tid < 64) {
        int t = tid >> 3, e = tid & 7;
        float a = bg3[e];
        for (int i = 0; i < G_HID_; i++)
            a = fmaf(s_g2[t][i], Wg3[i * E_ + e], a);
        s_lg[t][e] = a;
    }
    __syncthreads();

    if (tid < 8) {
        const int t   = tid;
        const int tok = t0 + t;
        float p[E_];
        float mx = s_lg[t][0];
        #pragma unroll
        for (int e = 1; e < E_; e++) mx = fmaxf(mx, s_lg[t][e]);
        float s = 0.f;
        #pragma unroll
        for (int e = 0; e < E_; e++) { p[e] = expf(s_lg[t][e] - mx); s += p[e]; }
        float inv = 1.f / s;
        float ent = 0.f;
        #pragma unroll
        for (int e = 0; e < E_; e++) { p[e] *= inv; ent -= p[e] * logf(p[e] + 1e-9f); }
        g_entropy[tok] = ent;

        int i1 = 0;
        #pragma unroll
        for (int e = 1; e < E_; e++) if (p[e] > p[i1]) i1 = e;
        int i2 = (i1 == 0) ? 1 : 0;
        #pragma unroll
        for (int e = 0; e < E_; e++) if (e != i1 && p[e] > p[i2]) i2 = e;

        float s1 = p[i1], s2 = p[i2];
        atomicAdd(&g_counts[i1], 1);
        atomicAdd(&g_counts[i2], 1);
        float denom = s1 + s2 + 1e-9f;
        g_tok_e[tok * 2 + 0] = i1;
        g_tok_e[tok * 2 + 1] = i2;
        g_tok_s[tok * 2 + 0] = s1 / denom;
        g_tok_s[tok * 2 + 1] = s2 / denom;

        long long idx_off = (long long)B_ * D_OUT_ + 1;
        long long sc_off  = idx_off + (long long)B_ * K_;
        if (out_sz >= sc_off + (long long)B_ * K_) {
            out[idx_off + tok * 2 + 0] = (float)i1;
            out[idx_off + tok * 2 + 1] = (float)i2;
            out[sc_off  + tok * 2 + 0] = s1;
            out[sc_off  + tok * 2 + 1] = s2;
        }
    }
}

__global__ void offsets_kernel() {
    if (threadIdx.x == 0 && blockIdx.x == 0) {
        int off = 0;
        for (int e = 0; e < E_; e++) {
            g_offsets[e] = off;
            g_cursor[e]  = off;
            off += g_counts[e];
        }
    }
}

__global__ void scatter_kernel() {
    int tok = blockIdx.x * blockDim.x + threadIdx.x;
    if (tok >= B_) return;
    #pragma unroll
    for (int k = 0; k < K_; k++) {
        int e = g_tok_e[tok * 2 + k];
        int pos = atomicAdd(&g_cursor[e], 1);
        g_pair_token[pos] = tok;
        g_tok_pos[tok * 2 + k] = pos;
    }
}

// ==================== MMA self-test ====================
__device__ __forceinline__ float stA(int i, int k) { return (float)(((i * 3 + k * 5) % 13) - 6); }
__device__ __forceinline__ float stB(int n, int k) { return (float)(((n * 7 + k * 11) % 9) - 4); }
__device__ __forceinline__ uint32_t stPack(float x, float y) {
    return (uint32_t)__bfloat16_as_ushort(__float2bfloat16_rn(x)) |
           ((uint32_t)__bfloat16_as_ushort(__float2bfloat16_rn(y)) << 16);
}

__global__ void mma_selftest() {
    const int lane = threadIdx.x;
    const int g = lane >> 2, t4 = lane & 3;

    uint32_t a0 = stPack(stA(g,     t4*2),     stA(g,     t4*2 + 1));
    uint32_t a1 = stPack(stA(g + 8, t4*2),     stA(g + 8, t4*2 + 1));
    uint32_t a2 = stPack(stA(g,     t4*2 + 8), stA(g,     t4*2 + 9));
    uint32_t a3 = stPack(stA(g + 8, t4*2 + 8), stA(g + 8, t4*2 + 9));
    uint32_t b0 = stPack(stB(g,     t4*2),     stB(g,     t4*2 + 1));
    uint32_t b1 = stPack(stB(g,     t4*2 + 8), stB(g,     t4*2 + 9));

    float c[4] = {0.f, 0.f, 0.f, 0.f};
    MMA_BF16(c, a0, a1, a2, a3, b0, b1);

    bool ok = true;
    #pragma unroll
    for (int h = 0; h < 4; h++) {
        int row = g + ((h >= 2) ? 8 : 0);
        int col = t4 * 2 + (h & 1);
        float r = 0.f;
        for (int k = 0; k < 16; k++) r += stA(row, k) * stB(col, k);
        ok = ok && (c[h] == r);
    }
    unsigned m = __ballot_sync(0xffffffffu, ok);
    if (lane == 0) g_mma_ok = (m == 0xffffffffu) ? 1 : 0;
}

// ==================== HMMA expert GEMM (round-6 engine) ====================
#define KC     32
#define A_ST   80
#define SA_HI  0
#define SA_LO  10240
#define SB_HI  20480
#define SB_LO  25600
#define SM_TOT 30720

template<int KDIM, int NDIM, int LAYER>
__global__ __launch_bounds__(256)
void moe_gemm(const float* __restrict__ bstack)
{
    if (g_mma_ok == 0) return;
    __shared__ __align__(16) char sbuf[SM_TOT];

    const int e   = blockIdx.z;
    const int cnt = g_counts[e];
    const int m0  = blockIdx.x * 128;
    if (m0 >= cnt) return;
    const int off = g_offsets[e];
    const int n0  = blockIdx.y * 64;
    const int tid = threadIdx.x;

    const __nv_bfloat16* Ah = (LAYER == 1) ? g_x_hi : (LAYER == 2 ? g_h1_hi : g_h2_hi);
    const __nv_bfloat16* Al = (LAYER == 1) ? g_x_lo : (LAYER == 2 ? g_h1_lo : g_h2_lo);
    const __nv_bfloat16* Wh = (LAYER == 1) ? g_w1t_hi : (LAYER == 2 ? g_w2t_hi : g_w3t_hi);
    const __nv_bfloat16* Wl = (LAYER == 1) ? g_w1t_lo : (LAYER == 2 ? g_w2t_lo : g_w3t_lo);

    const __nv_bfloat16* gsrc[6];
    uint32_t soff[6];
    #pragma unroll
    for (int j = 0; j < 6; j++) {
        int idx = j * 256 + tid;
        if (idx < 1024) {
            int local = idx & 511;
            int r = local >> 2, c = local & 3;
            int mr = m0 + r; if (mr >= cnt) mr = cnt - 1;
            size_t base = (LAYER == 1) ? (size_t)g_pair_token[off + mr] * KDIM
                                       : (size_t)(off + mr) * KDIM;
            gsrc[j] = ((idx < 512) ? Ah : Al) + base + c * 8;
            soff[j] = ((idx < 512) ? SA_HI : SA_LO) + r * A_ST + c * 16;
        } else {
            int local = (idx - 1024) & 255;
            int r = local >> 2, c = local & 3;
            const __nv_bfloat16* W = (idx < 1280) ? Wh : Wl;
            gsrc[j] = W + (size_t)e * NDIM * KDIM + (size_t)(n0 + r) * KDIM + c * 8;
            soff[j] = ((idx < 1280) ? SB_HI : SB_LO) + r * A_ST + c * 16;
        }
    }

    const int wid = tid >> 5, lane = tid & 31;
    const int g   = lane >> 2, t4 = lane & 3;
    const int wm  = (wid & 3) * 32;
    const int wn  = (wid >> 2) * 32;

    float acc[2][4][4];
    #pragma unroll
    for (int i = 0; i < 2; i++)
        #pragma unroll
        for (int j = 0; j < 4; j++)
            #pragma unroll
            for (int k = 0; k < 4; k++) acc[i][j][k] = 0.f;

    uint4 v[6];
    #pragma unroll
    for (int j = 0; j < 6; j++) v[j] = *reinterpret_cast<const uint4*>(gsrc[j]);

    constexpr int NT = KDIM / KC;
    for (int t = 0; t < NT; t++) {
        __syncthreads();
        #pragma unroll
        for (int j = 0; j < 6; j++)
            *reinterpret_cast<uint4*>(sbuf + soff[j]) = v[j];
        __syncthreads();
        if (t + 1 < NT) {
            #pragma unroll
            for (int j = 0; j < 6; j++)
                v[j] = *reinterpret_cast<const uint4*>(gsrc[j] + (t + 1) * KC);
        }

        #pragma unroll
        for (int kk = 0; kk < 2; kk++) {
            uint32_t ah[2][4], al[2][4], bh[2][4], bl[2][4];
            #pragma unroll
            for (int mt = 0; mt < 2; mt++) {
                uint32_t b = (uint32_t)(wm + mt * 16 + g) * A_ST + kk * 32 + t4 * 4;
                ah[mt][0] = *reinterpret_cast<const uint32_t*>(sbuf + SA_HI + b);
                ah[mt][1] = *reinterpret_cast<const uint32_t*>(sbuf + SA_HI + b + 8 * A_ST);
                ah[mt][2] = *reinterpret_cast<const uint32_t*>(sbuf + SA_HI + b + 16);
                ah[mt][3] = *reinterpret_cast<const uint32_t*>(sbuf + SA_HI + b + 8 * A_ST + 16);
                al[mt][0] = *reinterpret_cast<const uint32_t*>(sbuf + SA_LO + b);
                al[mt][1] = *reinterpret_cast<const uint32_t*>(sbuf + SA_LO + b + 8 * A_ST);
                al[mt][2] = *reinterpret_cast<const uint32_t*>(sbuf + SA_LO + b + 16);
                al[mt][3] = *reinterpret_cast<const uint32_t*>(sbuf + SA_LO + b + 8 * A_ST + 16);
            }
            #pragma unroll
            for (int np = 0; np < 2; np++) {
                uint32_t b = (uint32_t)(wn + np * 16 + g) * A_ST + kk * 32 + t4 * 4;
                bh[np][0] = *reinterpret_cast<const uint32_t*>(sbuf + SB_HI + b);
                bh[np][1] = *reinterpret_cast<const uint32_t*>(sbuf + SB_HI + b + 16);
                bh[np][2] = *reinterpret_cast<const uint32_t*>(sbuf + SB_HI + b + 8 * A_ST);
                bh[np][3] = *reinterpret_cast<const uint32_t*>(sbuf + SB_HI + b + 8 * A_ST + 16);
                bl[np][0] = *reinterpret_cast<const uint32_t*>(sbuf + SB_LO + b);
                bl[np][1] = *reinterpret_cast<const uint32_t*>(sbuf + SB_LO + b + 16);
                bl[np][2] = *reinterpret_cast<const uint32_t*>(sbuf + SB_LO + b + 8 * A_ST);
                bl[np][3] = *reinterpret_cast<const uint32_t*>(sbuf + SB_LO + b + 8 * A_ST + 16);
            }
            #pragma unroll
            for (int mt = 0; mt < 2; mt++)
                #pragma unroll
                for (int np = 0; np < 2; np++) {
                    MMA_BF16(acc[mt][np * 2],     ah[mt][0], ah[mt][1], ah[mt][2], ah[mt][3], bh[np][0], bh[np][1]);
                    MMA_BF16(acc[mt][np * 2],     ah[mt][0], ah[mt][1], ah[mt][2], ah[mt][3], bl[np][0], bl[np][1]);
                    MMA_BF16(acc[mt][np * 2],     al[mt][0], al[mt][1], al[mt][2], al[mt][3], bh[np][0], bh[np][1]);
                    MMA_BF16(acc[mt][np * 2 + 1], ah[mt][0], ah[mt][1], ah[mt][2], ah[mt][3], bh[np][2], bh[np][3]);
                    MMA_BF16(acc[mt][np * 2 + 1], ah[mt][0], ah[mt][1], ah[mt][2], ah[mt][3], bl[np][2], bl[np][3]);
                    MMA_BF16(acc[mt][np * 2 + 1], al[mt][0], al[mt][1], al[mt][2], al[mt][3], bh[np][2], bh[np][3]);
                }
        }
    }

    const int gid = lane >> 2, tig = lane & 3;
    __nv_bfloat16* Hh = (LAYER == 1) ? g_h1_hi : g_h2_hi;
    __nv_bfloat16* Hl = (LAYER == 1) ? g_h1_lo : g_h2_lo;

    #pragma unroll
    for (int mt = 0; mt < 2; mt++) {
        #pragma unroll
        for (int half = 0; half < 2; half++) {
            const int mr = m0 + wm + mt * 16 + gid + half * 8;
            if (mr >= cnt) continue;
            const size_t prow = (size_t)(off + mr);
            #pragma unroll
            for (int nt = 0; nt < 4; nt++) {
                const int col = n0 + wn + nt * 8 + tig * 2;
                float v0 = acc[mt][nt][half * 2 + 0] + bstack[(size_t)e * NDIM + col];
                float v1 = acc[mt][nt][half * 2 + 1] + bstack[(size_t)e * NDIM + col + 1];
                if (LAYER < 3) {
                    v0 = fmaxf(v0, 0.f);
                    v1 = fmaxf(v1, 0.f);
                    uint32_t hi, lo;
                    split2(v0, v1, hi, lo);
                    *reinterpret_cast<uint32_t*>(Hh + prow * NDIM + col) = hi;
                    *reinterpret_cast<uint32_t*>(Hl + prow * NDIM + col) = lo;
                } else {
                    float2 st; st.x = v0; st.y = v1;
                    *reinterpret_cast<float2*>(g_o_pair + prow * D_OUT_ + col) = st;
                }
            }
        }
    }
}

// ==================== probe: bisect staging / fragments / epilogue ============
__global__ __launch_bounds__(256)
void probe_kernel(const float* __restrict__ x,
                  const float* __restrict__ We1,
                  const float* __restrict__ be1)
{
    __shared__ __align__(16) char sbuf[SM_TOT];
    __shared__ int sh_e, sh_flags, sh_nz;
    const int tid = threadIdx.x;
    if (tid == 0) {
        int best = 0;
        for (int e = 1; e < E_; e++) if (g_counts[e] > g_counts[best]) best = e;
        sh_e = best; sh_flags = 0; sh_nz = 0;
    }
    __syncthreads();
    const int e   = sh_e;
    const int cnt = g_counts[e];
    const int off = g_offsets[e];
    const int KD  = D_IN_;
    const int ND  = D_HID_;

    // ---- staging, verbatim engine code (m0=0, n0=0, t=0, LAYER=1) ----
    const __nv_bfloat16* gsrc[6];
    uint32_t soff[6];
    #pragma unroll
    for (int j = 0; j < 6; j++) {
        int idx = j * 256 + tid;
        if (idx < 1024) {
            int local = idx & 511;
            int r = local >> 2, c = local & 3;
            int mr = r; if (mr >= cnt) mr = cnt - 1;
            size_t base = (size_t)g_pair_token[off + mr] * KD;
            gsrc[j] = ((idx < 512) ? g_x_hi : g_x_lo) + base + c * 8;
            soff[j] = ((idx < 512) ? SA_HI : SA_LO) + r * A_ST + c * 16;
        } else {
            int local = (idx - 1024) & 255;
            int r = local >> 2, c = local & 3;
            const __nv_bfloat16* W = (idx < 1280) ? g_w1t_hi : g_w1t_lo;
            gsrc[j] = W + (size_t)e * ND * KD + (size_t)r * KD + c * 8;
            soff[j] = ((idx < 1280) ? SB_HI : SB_LO) + r * A_ST + c * 16;
        }
    }
    uint4 v[6];
    #pragma unroll
    for (int j = 0; j < 6; j++) v[j] = *reinterpret_cast<const uint4*>(gsrc[j]);
    __syncthreads();
    #pragma unroll
    for (int j = 0; j < 6; j++)
        *reinterpret_cast<uint4*>(sbuf + soff[j]) = v[j];
    __syncthreads();

    int bad = 0;

    // F_A (bit 0): staged A tile bitwise vs gmem, independent index math
    for (int idx = tid; idx < 128 * 32; idx += 256) {
        int r = idx >> 5, k = idx & 31;
        int mr = (r >= cnt) ? cnt - 1 : r;
        size_t gi = (size_t)g_pair_token[off + mr] * KD + k;
        unsigned short eh = __bfloat16_as_ushort(g_x_hi[gi]);
        unsigned short el = __bfloat16_as_ushort(g_x_lo[gi]);
        unsigned short ah = *reinterpret_cast<unsigned short*>(sbuf + SA_HI + r * A_ST + k * 2);
        unsigned short al = *reinterpret_cast<unsigned short*>(sbuf + SA_LO + r * A_ST + k * 2);
        if (ah != eh || al != el) bad |= 1;
    }
    // F_B (bit 1): staged B tile
    for (int idx = tid; idx < 64 * 32; idx += 256) {
        int r = idx >> 5, k = idx & 31;
        size_t gi = (size_t)e * ND * KD + (size_t)r * KD + k;
        unsigned short eh = __bfloat16_as_ushort(g_w1t_hi[gi]);
        unsigned short el = __bfloat16_as_ushort(g_w1t_lo[gi]);
        unsigned short bhv = *reinterpret_cast<unsigned short*>(sbuf + SB_HI + r * A_ST + k * 2);
        unsigned short blv = *reinterpret_cast<unsigned short*>(sbuf + SB_LO + r * A_ST + k * 2);
        if (bhv != eh || blv != el) bad |= 2;
    }
    // F_C (bit 2): engine fragment loads + 6-MMA hi/lo group vs fp32 ref from smem
    {
        const int wid = tid >> 5, lane = tid & 31;
        const int g = lane >> 2, t4 = lane & 3;
        const int wm = (wid & 3) * 32, wn = (wid >> 2) * 32;
        uint32_t b = (uint32_t)(wm + g) * A_ST + t4 * 4;
        uint32_t a0h = *reinterpret_cast<const uint32_t*>(sbuf + SA_HI + b);
        uint32_t a1h = *reinterpret_cast<const uint32_t*>(sbuf + SA_HI + b + 8 * A_ST);
        uint32_t a2h = *reinterpret_cast<const uint32_t*>(sbuf + SA_HI + b + 16);
        uint32_t a3h = *reinterpret_cast<const uint32_t*>(sbuf + SA_HI + b + 8 * A_ST + 16);
        uint32_t a0l = *reinterpret_cast<const uint32_t*>(sbuf + SA_LO + b);
        uint32_t a1l = *reinterpret_cast<const uint32_t*>(sbuf + SA_LO + b + 8 * A_ST);
        uint32_t a2l = *reinterpret_cast<const uint32_t*>(sbuf + SA_LO + b + 16);
        uint32_t a3l = *reinterpret_cast<const uint32_t*>(sbuf + SA_LO + b + 8 * A_ST + 16);
        uint32_t bb = (uint32_t)(wn + g) * A_ST + t4 * 4;
        uint32_t b0h = *reinterpret_cast<const uint32_t*>(sbuf + SB_HI + bb);
        uint32_t b1h = *reinterpret_cast<const uint32_t*>(sbuf + SB_HI + bb + 16);
        uint32_t b2h = *reinterpret_cast<const uint32_t*>(sbuf + SB_HI + bb + 8 * A_ST);
        uint32_t b3h = *reinterpret_cast<const uint32_t*>(sbuf + SB_HI + bb + 8 * A_ST + 16);
        uint32_t b0l = *reinterpret_cast<const uint32_t*>(sbuf + SB_LO + bb);
        uint32_t b1l = *reinterpret_cast<const uint32_t*>(sbuf + SB_LO + bb + 16);
        uint32_t b2l = *reinterpret_cast<const uint32_t*>(sbuf + SB_LO + bb + 8 * A_ST);
        uint32_t b3l = *reinterpret_cast<const uint32_t*>(sbuf + SB_LO + bb + 8 * A_ST + 16);

        float c0[4] = {0,0,0,0}, c1[4] = {0,0,0,0};
        MMA_BF16(c0, a0h, a1h, a2h, a3h, b0h, b1h);
        MMA_BF16(c0, a0h, a1h, a2h, a3h, b0l, b1l);
        MMA_BF16(c0, a0l, a1l, a2l, a3l, b0h, b1h);
        MMA_BF16(c1, a0h, a1h, a2h, a3h, b2h, b3h);
        MMA_BF16(c1, a0h, a1h, a2h, a3h, b2l, b3l);
        MMA_BF16(c1, a0l, a1l, a2l, a3l, b2h, b3h);

        #pragma unroll
        for (int h = 0; h < 4; h++) {
            int row  = wm + g + ((h >= 2) ? 8 : 0);
            int col0 = wn + t4 * 2 + (h & 1);
            float r0 = 0.f, r1 = 0.f;
            for (int k = 0; k < 16; k++) {
                float avh = __bfloat162float(*reinterpret_cast<__nv_bfloat16*>(sbuf + SA_HI + row * A_ST + k * 2));
                float avl = __bfloat162float(*reinterpret_cast<__nv_bfloat16*>(sbuf + SA_LO + row * A_ST + k * 2));
                float b0v = __bfloat162float(*reinterpret_cast<__nv_bfloat16*>(sbuf + SB_HI + col0 * A_ST + k * 2));
                float b0w = __bfloat162float(*reinterpret_cast<__nv_bfloat16*>(sbuf + SB_LO + col0 * A_ST + k * 2));
                float b1v = __bfloat162float(*reinterpret_cast<__nv_bfloat16*>(sbuf + SB_HI + (col0 + 8) * A_ST + k * 2));
                float b1w = __bfloat162float(*reinterpret_cast<__nv_bfloat16*>(sbuf + SB_LO + (col0 + 8) * A_ST + k * 2));
                r0 += avh * b0v + avh * b0w + avl * b0v;
                r1 += avh * b1v + avh * b1w + avl * b1v;
            }
            if (fabsf(c0[h] - r0) > 1e-4f + 1e-3f * fabsf(r0)) bad |= 4;
            if (fabsf(c1[h] - r1) > 1e-4f + 1e-3f * fabsf(r1)) bad |= 4;
        }
    }
    // F_W (bit 3) + F_Z: engine L1 output row 0 vs fp32 reference
    if (tid < 64) {
        int tok0 = g_pair_token[off + 0];
        float s = be1[(size_t)e * ND + tid];
        for (int k = 0; k < KD; k++)
            s = fmaf(x[(size_t)tok0 * KD + k], We1[(size_t)e * KD * ND + (size_t)k * ND + tid], s);
        s = fmaxf(s, 0.f);
        size_t hrow = (size_t)(off + 0) * ND;
        float got = __bfloat162float(g_h1_hi[hrow + tid]) + __bfloat162float(g_h1_lo[hrow + tid]);
        if (fabsf(got - s) > 5e-3f * (fabsf(s) + 0.1f)) bad |= 8;
        if (__bfloat16_as_ushort(g_h1_hi[hrow + tid]) != 0) atomicAdd(&sh_nz, 1);
    }
    atomicOr(&sh_flags, bad);
    __syncthreads();
    if (tid == 0) {
        int f = sh_flags;
        if (sh_nz == 0) f |= 16;   // F_Z: output row all-zero (engine wrote nothing)
        g_flags = f;
    }
}

// ==================== per-layer verify ====================
template<int L>
__global__ __launch_bounds__(256)
void verify_layer(const float* __restrict__ x,
                  const float* __restrict__ W, const float* __restrict__ b)
{
    constexpr int KD = (L == 1) ? D_IN_ : D_HID_;
    constexpr int ND = (L == 3) ? D_OUT_ : D_HID_;
    __shared__ float a_in[KD];
    __shared__ int s_bad;
    const int tid = threadIdx.x;
    if (tid == 0) s_bad = 0;
    __syncthreads();

    if (g_mma_ok == 0) {
        if (tid == 0) g_badL[L - 1] = 1;
        return;
    }

    const int r = (blockIdx.x == 0) ? 0 : 101;
    int e = 0;
    for (int i = 0; i < E_; i++)
        if (g_offsets[i] <= r && r < g_offsets[i] + g_counts[i]) e = i;

    if (L == 1) {
        const int tok = g_pair_token[r];
        for (int i = tid; i < KD; i += 256) a_in[i] = x[(size_t)tok * KD + i];
    } else {
        const __nv_bfloat16* hh = (L == 2) ? g_h1_hi : g_h2_hi;
        const __nv_bfloat16* hl = (L == 2) ? g_h1_lo : g_h2_lo;
        for (int i = tid; i < KD; i += 256)
            a_in[i] = __bfloat162float(hh[(size_t)r * KD + i])
                    + __bfloat162float(hl[(size_t)r * KD + i]);
    }
    __syncthreads();

    const int j = tid;
    float s = b[(size_t)e * ND + j];
    const float* w = W + (size_t)e * KD * ND + j;
    for (int k = 0; k < KD; k++) s = fmaf(a_in[k], w[(size_t)k * ND], s);
    if (L < 3) s = fmaxf(s, 0.f);

    float got;
    if (L == 1)
        got = __bfloat162float(g_h1_hi[(size_t)r * ND + j]) + __bfloat162float(g_h1_lo[(size_t)r * ND + j]);
    else if (L == 2)
        got = __bfloat162float(g_h2_hi[(size_t)r * ND + j]) + __bfloat162float(g_h2_lo[(size_t)r * ND + j]);
    else
        got = g_o_pair[(size_t)r * ND + j];

    if (!(fabsf(got - s) <= 5e-3f * (fabsf(s) + 0.1f))) s_bad = 1;
    __syncthreads();
    if (tid == 0 && s_bad) g_badL[L - 1] = 1;
}

// ==================== fp32 repair GEMM ====================
#define BM 128
#define BN 128
#define BK 8

template<int KDIM, int NDIM, int LAYER>
__global__ __launch_bounds__(256, 2)
void repair_gemm(const float* __restrict__ xptr,
                 const float* __restrict__ Wstack,
                 const float* __restrict__ bstack)
{
    if (g_badL[LAYER - 1] == 0) return;

    const int e   = blockIdx.z;
    const int cnt = g_counts[e];
    const int m0  = blockIdx.y * BM;
    if (m0 >= cnt) return;
    const int off = g_offsets[e];
    const int n0  = blockIdx.x * BN;

    const float* __restrict__ Wb = Wstack + (size_t)e * KDIM * NDIM;

    __shared__ __align__(16) float As[2][BK][BM];
    __shared__ __align__(16) float Bs[2][BK][BN];

    const int tid   = threadIdx.x;
    const int a_row = tid >> 1;
    const int a_kq  = (tid & 1) << 2;
    const int b_k   = tid >> 5;
    const int b_n   = (tid & 31) << 2;

    int m  = m0 + a_row;
    int mm = (m < cnt) ? m : (cnt - 1);

    const float* Axr = nullptr;
    const __nv_bfloat16* Ahr = nullptr;
    const __nv_bfloat16* Alr = nullptr;
    if (LAYER == 1) {
        Axr = xptr + (size_t)g_pair_token[off + mm] * KDIM;
    } else {
        Ahr = ((LAYER == 2) ? g_h1_hi : g_h2_hi) + (size_t)(off + mm) * KDIM;
        Alr = ((LAYER == 2) ? g_h1_lo : g_h2_lo) + (size_t)(off + mm) * KDIM;
    }

    auto loadA = [&](int k) -> float4 {
        if (LAYER == 1) return *reinterpret_cast<const float4*>(Axr + k);
        uint2 uh = *reinterpret_cast<const uint2*>(Ahr + k);
        uint2 ul = *reinterpret_cast<const uint2*>(Alr + k);
        float4 r;
        r.x = bfu(uh.x) + bfu(ul.x);
        r.y = bfu(uh.x >> 16) + bfu(ul.x >> 16);
        r.z = bfu(uh.y) + bfu(ul.y);
        r.w = bfu(uh.y >> 16) + bfu(ul.y >> 16);
        return r;
    };

    const int tx = tid & 15;
    const int ty = tid >> 4;

    float acc[8][8];
    #pragma unroll
    for (int i = 0; i < 8; i++)
        #pragma unroll
        for (int j = 0; j < 8; j++) acc[i][j] = 0.f;

    {
        float4 av = loadA(a_kq);
        float4 bv = *reinterpret_cast<const float4*>(Wb + (size_t)b_k * NDIM + n0 + b_n);
        As[0][a_kq + 0][a_row] = av.x;
        As[0][a_kq + 1][a_row] = av.y;
        As[0][a_kq + 2][a_row] = av.z;
        As[0][a_kq + 3][a_row] = av.w;
        *reinterpret_cast<float4*>(&Bs[0][b_k][b_n]) = bv;
    }
    __syncthreads();

    const int ntiles = KDIM / BK;
    for (int t = 0; t < ntiles; ++t) {
        const int cur = t & 1;
        const int nxt = cur ^ 1;
        float4 an, bn;
        if (t + 1 < ntiles) {
            const int k0 = (t + 1) * BK;
            an = loadA(k0 + a_kq);
            bn = *reinterpret_cast<const float4*>(Wb + (size_t)(k0 + b_k) * NDIM + n0 + b_n);
        }
        #pragma unroll
        for (int kk = 0; kk < BK; kk++) {
            float ar[8], br[8];
            *reinterpret_cast<float4*>(&ar[0]) = *reinterpret_cast<const float4*>(&As[cur][kk][ty * 8]);
            *reinterpret_cast<float4*>(&ar[4]) = *reinterpret_cast<const float4*>(&As[cur][kk][ty * 8 + 4]);
            *reinterpret_cast<float4*>(&br[0]) = *reinterpret_cast<const float4*>(&Bs[cur][kk][tx * 8]);
            *reinterpret_cast<float4*>(&br[4]) = *reinterpret_cast<const float4*>(&Bs[cur][kk][tx * 8 + 4]);
            #pragma unroll
            for (int i = 0; i < 8; i++)
                #pragma unroll
                for (int j = 0; j < 8; j++)
                    acc[i][j] = fmaf(ar[i], br[j], acc[i][j]);
        }
        if (t + 1 < ntiles) {
            As[nxt][a_kq + 0][a_row] = an.x;
            As[nxt][a_kq + 1][a_row] = an.y;
            As[nxt][a_kq + 2][a_row] = an.z;
            As[nxt][a_kq + 3][a_row] = an.w;
            *reinterpret_cast<float4*>(&Bs[nxt][b_k][b_n]) = bn;
        }
        __syncthreads();
    }

    const int col0 = n0 + tx * 8;
    float bias[8];
    #pragma unroll
    for (int j = 0; j < 8; j++) bias[j] = bstack[(size_t)e * NDIM + col0 + j];

    __nv_bfloat16* Hh = (LAYER == 1) ? g_h1_hi : g_h2_hi;
    __nv_bfloat16* Hl = (LAYER == 1) ? g_h1_lo : g_h2_lo;

    #pragma unroll
    for (int i = 0; i < 8; i++) {
        int mr = m0 + ty * 8 + i;
        if (mr >= cnt) continue;
        const size_t prow = (size_t)(off + mr);
        if (LAYER < 3) {
            #pragma unroll
            for (int jp = 0; jp < 4; jp++) {
                float v0 = fmaxf(acc[i][jp * 2 + 0] + bias[jp * 2 + 0], 0.f);
                float v1 = fmaxf(acc[i][jp * 2 + 1] + bias[jp * 2 + 1], 0.f);
                uint32_t hi, lo;
                split2(v0, v1, hi, lo);
                *reinterpret_cast<uint32_t*>(Hh + prow * NDIM + col0 + jp * 2) = hi;
                *reinterpret_cast<uint32_t*>(Hl + prow * NDIM + col0 + jp * 2) = lo;
            }
        } else {
            float* orow = g_o_pair + prow * D_OUT_ + col0;
            #pragma unroll
            for (int j = 0; j < 8; j++)
                orow[j] = acc[i][j] + bias[j];
        }
    }
}

// ==================== diagnostic spin ====================
__device__ __forceinline__ unsigned long long gtimer() {
    unsigned long long t;
    asm volatile("mov.u64 %0, %%globaltimer;" : "=l"(t));
    return t;
}

__global__ void spin_kernel() {
    if (threadIdx.x != 0) return;
    unsigned long long add = 0;
    if (g_mma_ok == 0) add += 32000000ULL;
    int f = g_flags;
    if (f & 1)  add += 1000000ULL;    // F_A: staged A tile wrong
    if (f & 2)  add += 2000000ULL;    // F_B: staged B tile wrong
    if (f & 4)  add += 4000000ULL;    // F_C: fragment path / MMA-from-smem wrong
    if (f & 8)  add += 8000000ULL;    // F_W: L1 output wrong
    if (f & 16) add += 16000000ULL;   // F_Z: L1 output never written
    if (add) {
        unsigned long long t0 = gtimer();
        while (gtimer() - t0 < add) {}
    }
}

// ==================== combine + finalize ====================
__global__ __launch_bounds__(256)
void combine_kernel(float* __restrict__ out)
{
    int i = blockIdx.x * 256 + threadIdx.x;
    int tok = i >> 10, c = i & 1023;
    float v = g_tok_s[tok * 2 + 0] * g_o_pair[(size_t)g_tok_pos[tok * 2 + 0] * D_OUT_ + c]
            + g_tok_s[tok * 2 + 1] * g_o_pair[(size_t)g_tok_pos[tok * 2 + 1] * D_OUT_ + c];
    out[i] = v;
}

__global__ __launch_bounds__(1024)
void finalize_kernel(float* __restrict__ out, long long out_sz)
{
    __shared__ float red[1024];
    const int tid = threadIdx.x;
    float s = 0.f;
    for (int i = tid; i < B_; i += 1024) s += g_entropy[i];
    red[tid] = s;
    __syncthreads();
    for (int st = 512; st > 0; st >>= 1) {
        if (tid < st) red[tid] += red[tid + st];
        __syncthreads();
    }
    if (tid == 0) {
        float ent_mean = red[0] / (float)B_;
        float load[E_];
        float mean = 0.f;
        for (int e = 0; e < E_; e++) {
            load[e] = (float)g_counts[e] / ((float)B_ + 1e-9f);
            mean += load[e];
        }
        mean /= (float)E_;
        float var = 0.f;
        for (int e = 0; e < E_; e++) {
            float d = load[e] - mean;
            var += d * d;
        }
        var /= (float)(E_ - 1);
        float aux = 5.0f * var + 0.1f * ent_mean;
        long long aux_off = (long long)B_ * D_OUT_;
        if (out_sz > aux_off) out[aux_off] = aux;
    }
}

// ==================== launch ====================
extern "C" void kernel_launch(void* const* d_in, const int* in_sizes, int n_in,
                              void* d_out, int out_size)
{
    const float* x   = (const float*)d_in[0];
    const float* We1 = (const float*)d_in[1];
    const float* be1 = (const float*)d_in[2];
    const float* We2 = (const float*)d_in[3];
    const float* be2 = (const float*)d_in[4];
    const float* We3 = (const float*)d_in[5];
    const float* be3 = (const float*)d_in[6];
    const float* Wg1 = (const float*)d_in[7];
    const float* bg1 = (const float*)d_in[8];
    const float* Wg2 = (const float*)d_in[9];
    const float* bg2 = (const float*)d_in[10];
    const float* Wg3 = (const float*)d_in[11];
    const float* bg3 = (const float*)d_in[12];
    float* out = (float*)d_out;
    long long out_sz = (long long)out_size;

    init_kernel<<<1, 32>>>();
    gate_kernel<<<B_ / 8, 128>>>(x, Wg1, bg1, Wg2, bg2, Wg3, bg3, out, out_sz);
    offsets_kernel<<<1, 32>>>();
    scatter_kernel<<<(B_ + 255) / 256, 256>>>();

    prep_x<<<(B_ * D_IN_) / 256, 256>>>(x);
    prep_w<<<dim3(D_HID_ / 32, D_IN_  / 32, E_), dim3(32, 8)>>>(We1, g_w1t_hi, g_w1t_lo, D_IN_,  D_HID_);
    prep_w<<<dim3(D_HID_ / 32, D_HID_ / 32, E_), dim3(32, 8)>>>(We2, g_w2t_hi, g_w2t_lo, D_HID_, D_HID_);
    prep_w<<<dim3(D_OUT_ / 32, D_HID_ / 32, E_), dim3(32, 8)>>>(We3, g_w3t_hi, g_w3t_lo, D_HID_, D_OUT_);

    mma_selftest<<<1, 32>>>();
    zero_h1<<<1024, 256>>>();   // poison so F_W/F_Z are meaningful on every replay

    const int max_mt = B_ / 128;

    moe_gemm<D_IN_,  D_HID_, 1><<<dim3(max_mt, D_HID_ / 64, E_), 256>>>(be1);
    probe_kernel<<<1, 256>>>(x, We1, be1);
    verify_layer<1><<<2, 256>>>(x, We1, be1);
    repair_gemm<D_IN_,  D_HID_, 1><<<dim3(D_HID_ / BN, max_mt, E_), 256>>>(x, We1, be1);

    moe_gemm<D_HID_, D_HID_, 2><<<dim3(max_mt, D_HID_ / 64, E_), 256>>>(be2);
    verify_layer<2><<<2, 256>>>(x, We2, be2);
    repair_gemm<D_HID_, D_HID_, 2><<<dim3(D_HID_ / BN, max_mt, E_), 256>>>(x, We2, be2);

    moe_gemm<D_HID_, D_OUT_, 3><<<dim3(max_mt, D_OUT_ / 64, E_), 256>>>(be3);
    verify_layer<3><<<2, 256>>>(x, We3, be3);
    repair_gemm<D_HID_, D_OUT_, 3><<<dim3(D_OUT_ / BN, max_mt, E_), 256>>>(x, We3, be3);

    spin_kernel<<<1, 32>>>();

    combine_kernel<<<(B_ * D_OUT_) / 256, 256>>>(out);
    finalize_kernel<<<1, 1024>>>(out, out_sz);
}

// round 9
// speedup vs baseline: 2.7787x; 2.7787x over previous
#include <cuda_runtime.h>
#include <cuda_bf16.h>
#include <math.h>
#include <stdint.h>

#define E_     8
#define B_     4096
#define D_IN_  1024
#define D_HID_ 2048
#define D_OUT_ 1024
#define G_HID_ 128
#define K_     2

#define PAIR_CAP 9216
#define MBT      (PAIR_CAP / 16)    // 576
#define KT1      (D_IN_ / 16)       // 64
#define KT2      (D_HID_ / 16)      // 128
#define NB12     (D_HID_ / 8)       // 256
#define NB3      (D_OUT_ / 8)       // 128

// ==================== helpers ====================
__device__ __forceinline__ void split2(float a, float b, uint32_t& hi, uint32_t& lo) {
    __nv_bfloat16 ha = __float2bfloat16_rn(a), hb = __float2bfloat16_rn(b);
    float ra = a - __bfloat162float(ha);
    float rb = b - __bfloat162float(hb);
    __nv_bfloat16 la = __float2bfloat16_rn(ra), lb = __float2bfloat16_rn(rb);
    hi = (uint32_t)__bfloat16_as_ushort(ha) | ((uint32_t)__bfloat16_as_ushort(hb) << 16);
    lo = (uint32_t)__bfloat16_as_ushort(la) | ((uint32_t)__bfloat16_as_ushort(lb) << 16);
}
__device__ __forceinline__ float bfu(uint32_t u) {
    return __bfloat162float(__ushort_as_bfloat16((unsigned short)(u & 0xffffu)));
}
// word index in an AF array (fragment layout). KTn = k16-blocks per row.
__device__ __forceinline__ size_t af_widx(int row, int col, int KTn) {
    int mblk = row >> 4, rb = row & 15;
    int kblk = col >> 4, kin = col & 15;
    int lane = ((rb & 7) << 2) | ((kin >> 1) & 3);
    int w    = (rb >> 3) | ((kin >> 3) << 1);
    return (((((size_t)mblk * KTn + kblk) * 32 + lane)) << 2) | (size_t)w;
}
__device__ __forceinline__ float af_read(const uint32_t* hi, const uint32_t* lo,
                                         int row, int col, int KTn) {
    size_t wi = af_widx(row, col, KTn);
    int sh = (col & 1) * 16;
    return bfu(hi[wi] >> sh) + bfu(lo[wi] >> sh);
}

#define MMA_BF16(c, a0, a1, a2, a3, b0, b1) \
    asm volatile("mma.sync.aligned.m16n8k16.row.col.f32.bf16.bf16.f32 " \
        "{%0,%1,%2,%3},{%4,%5,%6,%7},{%8,%9},{%0,%1,%2,%3};" \
        : "+f"((c)[0]), "+f"((c)[1]), "+f"((c)[2]), "+f"((c)[3]) \
        : "r"(a0), "r"(a1), "r"(a2), "r"(a3), "r"(b0), "r"(b1))

// ==================== device scratch ====================
__device__ int   g_counts[E_];
__device__ int   g_offsets[E_];
__device__ int   g_cursor[E_];
__device__ int   g_tok_e[B_ * K_];
__device__ float g_tok_s[B_ * K_];
__device__ int   g_tok_pos[B_ * K_];
__device__ int   g_pair_token[PAIR_CAP];
__device__ float g_entropy[B_];
__device__ int   g_mma_ok;
__device__ int   g_badL[3];

__device__ __align__(16) uint32_t g_afx_hi[(size_t)MBT * KT1 * 32 * 4];
__device__ __align__(16) uint32_t g_afx_lo[(size_t)MBT * KT1 * 32 * 4];
__device__ __align__(16) uint32_t g_afh1_hi[(size_t)MBT * KT2 * 32 * 4];
__device__ __align__(16) uint32_t g_afh1_lo[(size_t)MBT * KT2 * 32 * 4];
__device__ __align__(16) uint32_t g_afh2_hi[(size_t)MBT * KT2 * 32 * 4];
__device__ __align__(16) uint32_t g_afh2_lo[(size_t)MBT * KT2 * 32 * 4];
__device__ __align__(16) uint32_t g_wf1_hi[(size_t)E_ * NB12 * KT1 * 32 * 2];
__device__ __align__(16) uint32_t g_wf1_lo[(size_t)E_ * NB12 * KT1 * 32 * 2];
__device__ __align__(16) uint32_t g_wf2_hi[(size_t)E_ * NB12 * KT2 * 32 * 2];
__device__ __align__(16) uint32_t g_wf2_lo[(size_t)E_ * NB12 * KT2 * 32 * 2];
__device__ __align__(16) uint32_t g_wf3_hi[(size_t)E_ * NB3 * KT2 * 32 * 2];
__device__ __align__(16) uint32_t g_wf3_lo[(size_t)E_ * NB3 * KT2 * 32 * 2];
__device__ __align__(16) float g_o_pair[(size_t)PAIR_CAP * D_OUT_];

// ==================== small kernels ====================
__global__ void init_kernel() {
    int i = blockIdx.x * 256 + threadIdx.x;
    if (i < PAIR_CAP) g_pair_token[i] = 0;
    if (i < E_) { g_counts[i] = 0; g_cursor[i] = 0; }
    if (i == 0) { g_mma_ok = 0; g_badL[0] = 0; g_badL[1] = 0; g_badL[2] = 0; }
}

__global__ __launch_bounds__(128)
void gate_kernel(const float* __restrict__ x,
                 const float* __restrict__ Wg1, const float* __restrict__ bg1,
                 const float* __restrict__ Wg2, const float* __restrict__ bg2,
                 const float* __restrict__ Wg3, const float* __restrict__ bg3,
                 float* __restrict__ out, long long out_sz)
{
    __shared__ __align__(16) float xs[8][D_IN_];
    __shared__ float s_g1[8][G_HID_];
    __shared__ float s_g2[8][G_HID_];
    __shared__ float s_lg[8][E_];

    const int tid = threadIdx.x;
    const int t0  = blockIdx.x * 8;

    const float4* xg  = reinterpret_cast<const float4*>(x + (size_t)t0 * D_IN_);
    float4*       xsv = reinterpret_cast<float4*>(&xs[0][0]);
    #pragma unroll
    for (int i = 0; i < (8 * D_IN_ / 4) / 128; i++)
        xsv[tid + i * 128] = xg[tid + i * 128];
    __syncthreads();

    float acc[8];
    #pragma unroll
    for (int t = 0; t < 8; t++) acc[t] = 0.f;
    for (int i = 0; i < D_IN_; i++) {
        float w = Wg1[i * G_HID_ + tid];
        #pragma unroll
        for (int t = 0; t < 8; t++) acc[t] = fmaf(xs[t][i], w, acc[t]);
    }
    {
        float b = bg1[tid];
        #pragma unroll
        for (int t = 0; t < 8; t++) s_g1[t][tid] = fmaxf(acc[t] + b, 0.f);
    }
    __syncthreads();

    #pragma unroll
    for (int t = 0; t < 8; t++) acc[t] = 0.f;
    for (int i = 0; i < G_HID_; i++) {
        float w = Wg2[i * G_HID_ + tid];
        #pragma unroll
        for (int t = 0; t < 8; t++) acc[t] = fmaf(s_g1[t][i], w, acc[t]);
    }
    {
        float b = bg2[tid];
        #pragma unroll
        for (int t = 0; t < 8; t++) s_g2[t][tid] = fmaxf(acc[t] + b, 0.f);
    }
    __syncthreads();

    if (tid < 64) {
        int t = tid >> 3, e = tid & 7;
        float a = bg3[e];
        for (int i = 0; i < G_HID_; i++)
            a = fmaf(s_g2[t][i], Wg3[i * E_ + e], a);
        s_lg[t][e] = a;
    }
    __syncthreads();

    if (tid < 8) {
        const int t   = tid;
        const int tok = t0 + t;
        float p[E_];
        float mx = s_lg[t][0];
        #pragma unroll
        for (int e = 1; e < E_; e++) mx = fmaxf(mx, s_lg[t][e]);
        float s = 0.f;
        #pragma unroll
        for (int e = 0; e < E_; e++) { p[e] = expf(s_lg[t][e] - mx); s += p[e]; }
        float inv = 1.f / s;
        float ent = 0.f;
        #pragma unroll
        for (int e = 0; e < E_; e++) { p[e] *= inv; ent -= p[e] * logf(p[e] + 1e-9f); }
        g_entropy[tok] = ent;

        int i1 = 0;
        #pragma unroll
        for (int e = 1; e < E_; e++) if (p[e] > p[i1]) i1 = e;
        int i2 = (i1 == 0) ? 1 : 0;
        #pragma unroll
        for (int e = 0; e < E_; e++) if (e != i1 && p[e] > p[i2]) i2 = e;

        float s1 = p[i1], s2 = p[i2];
        atomicAdd(&g_counts[i1], 1);
        atomicAdd(&g_counts[i2], 1);
        float denom = s1 + s2 + 1e-9f;
        g_tok_e[tok * 2 + 0] = i1;
        g_tok_e[tok * 2 + 1] = i2;
        g_tok_s[tok * 2 + 0] = s1 / denom;
        g_tok_s[tok * 2 + 1] = s2 / denom;

        long long idx_off = (long long)B_ * D_OUT_ + 1;
        long long sc_off  = idx_off + (long long)B_ * K_;
        if (out_sz >= sc_off + (long long)B_ * K_) {
            out[idx_off + tok * 2 + 0] = (float)i1;
            out[idx_off + tok * 2 + 1] = (float)i2;
            out[sc_off  + tok * 2 + 0] = s1;
            out[sc_off  + tok * 2 + 1] = s2;
        }
    }
}

__global__ void offsets_kernel() {
    if (threadIdx.x == 0 && blockIdx.x == 0) {
        int off = 0;
        for (int e = 0; e < E_; e++) {
            g_offsets[e] = off;
            g_cursor[e]  = off;
            off += (g_counts[e] + 127) & ~127;   // pad to 128 for fragment alignment
        }
    }
}

__global__ void scatter_kernel() {
    int tok = blockIdx.x * blockDim.x + threadIdx.x;
    if (tok >= B_) return;
    #pragma unroll
    for (int k = 0; k < K_; k++) {
        int e = g_tok_e[tok * 2 + k];
        int pos = atomicAdd(&g_cursor[e], 1);
        g_pair_token[pos] = tok;
        g_tok_pos[tok * 2 + k] = pos;
    }
}

// x -> fragment layout (hi/lo), gathered by pair token
__global__ __launch_bounds__(256)
void prep_af1(const float* __restrict__ x) {
    int linear = blockIdx.x * 256 + threadIdx.x;   // (mblk*KT1 + kblk)*32 + lane
    if (linear >= MBT * KT1 * 32) return;
    int lane = linear & 31;
    int q = linear >> 5;
    int kblk = q % KT1, mblk = q / KT1;
    int g = lane >> 2, t4 = lane & 3;
    uint32_t hi[4], lo[4];
    #pragma unroll
    for (int w = 0; w < 4; w++) {
        int row = mblk * 16 + g + (w & 1) * 8;
        int k   = kblk * 16 + 2 * t4 + (w & 2) * 4;
        int tok = g_pair_token[row];
        float f0 = x[(size_t)tok * D_IN_ + k];
        float f1 = x[(size_t)tok * D_IN_ + k + 1];
        split2(f0, f1, hi[w], lo[w]);
    }
    size_t base = (size_t)linear * 4;
    *reinterpret_cast<uint4*>(&g_afx_hi[base]) = make_uint4(hi[0], hi[1], hi[2], hi[3]);
    *reinterpret_cast<uint4*>(&g_afx_lo[base]) = make_uint4(lo[0], lo[1], lo[2], lo[3]);
}

// W[e][KD][ND] -> fragment-layout WF (b0,b1 per lane), hi/lo
__global__ __launch_bounds__(256)
void prep_wf(const float* __restrict__ W, uint32_t* __restrict__ WFhi,
             uint32_t* __restrict__ WFlo, int KD, int ND)
{
    int KT = KD / 16, NB = ND / 8;
    long long linear = (long long)blockIdx.x * 256 + threadIdx.x;
    if (linear >= (long long)E_ * NB * KT * 32) return;
    int lane = (int)(linear & 31);
    long long q = linear >> 5;
    int kblk = (int)(q % KT); q /= KT;
    int nblk = (int)(q % NB); int e = (int)(q / NB);
    int n = nblk * 8 + (lane >> 2);
    int k0 = kblk * 16 + 2 * (lane & 3);
    #pragma unroll
    for (int w = 0; w < 2; w++) {
        int k = k0 + w * 8;
        float f0 = W[((size_t)e * KD + k)     * ND + n];
        float f1 = W[((size_t)e * KD + k + 1) * ND + n];
        uint32_t hi, lo;
        split2(f0, f1, hi, lo);
        WFhi[(size_t)linear * 2 + w] = hi;
        WFlo[(size_t)linear * 2 + w] = lo;
    }
}

// ==================== MMA self-test (register-only, hardware-proven) ==========
__device__ __forceinline__ float stA(int i, int k) { return (float)(((i * 3 + k * 5) % 13) - 6); }
__device__ __forceinline__ float stB(int n, int k) { return (float)(((n * 7 + k * 11) % 9) - 4); }
__device__ __forceinline__ uint32_t stPack(float x, float y) {
    return (uint32_t)__bfloat16_as_ushort(__float2bfloat16_rn(x)) |
           ((uint32_t)__bfloat16_as_ushort(__float2bfloat16_rn(y)) << 16);
}
__global__ void mma_selftest() {
    const int lane = threadIdx.x;
    const int g = lane >> 2, t4 = lane & 3;
    uint32_t a0 = stPack(stA(g,     t4*2),     stA(g,     t4*2 + 1));
    uint32_t a1 = stPack(stA(g + 8, t4*2),     stA(g + 8, t4*2 + 1));
    uint32_t a2 = stPack(stA(g,     t4*2 + 8), stA(g,     t4*2 + 9));
    uint32_t a3 = stPack(stA(g + 8, t4*2 + 8), stA(g + 8, t4*2 + 9));
    uint32_t b0 = stPack(stB(g,     t4*2),     stB(g,     t4*2 + 1));
    uint32_t b1 = stPack(stB(g,     t4*2 + 8), stB(g,     t4*2 + 9));
    float c[4] = {0.f, 0.f, 0.f, 0.f};
    MMA_BF16(c, a0, a1, a2, a3, b0, b1);
    bool ok = true;
    #pragma unroll
    for (int h = 0; h < 4; h++) {
        int row = g + ((h >= 2) ? 8 : 0);
        int col = t4 * 2 + (h & 1);
        float r = 0.f;
        for (int k = 0; k < 16; k++) r += stA(row, k) * stB(col, k);
        ok = ok && (c[h] == r);
    }
    unsigned m = __ballot_sync(0xffffffffu, ok);
    if (lane == 0) g_mma_ok = (m == 0xffffffffu) ? 1 : 0;
}

// ==================== fragment-layout HMMA GEMM (no smem) ====================
// CTA: 64 m x 256 n, 8 warps (2 m-warps x 4 n-warps). Warp: 32m x 64n.
template<int KDIM, int NDIM, int LAYER>
__global__ __launch_bounds__(256, 1)
void moe_gemm(const float* __restrict__ bstack)
{
    if (g_mma_ok == 0) return;
    constexpr int KT  = KDIM / 16;
    constexpr int NB  = NDIM / 8;
    constexpr int KTn = NDIM / 16;

    const int e   = blockIdx.z;
    const int cnt = g_counts[e];
    const int m0  = blockIdx.x * 64;
    if (m0 >= cnt) return;
    const int off = g_offsets[e];
    const int n0  = blockIdx.y * 256;

    const int tid = threadIdx.x, wid = tid >> 5, lane = tid & 31;
    const int g = lane >> 2, t4 = lane & 3;
    const int wm = (wid & 1) * 32;
    const int wn = (wid >> 1) * 64;

    const uint32_t* __restrict__ AH = (LAYER == 1) ? g_afx_hi : (LAYER == 2 ? g_afh1_hi : g_afh2_hi);
    const uint32_t* __restrict__ AL = (LAYER == 1) ? g_afx_lo : (LAYER == 2 ? g_afh1_lo : g_afh2_lo);
    const uint32_t* __restrict__ WH = (LAYER == 1) ? g_wf1_hi : (LAYER == 2 ? g_wf2_hi : g_wf3_hi);
    const uint32_t* __restrict__ WL = (LAYER == 1) ? g_wf1_lo : (LAYER == 2 ? g_wf2_lo : g_wf3_lo);

    size_t aidx[2];
    #pragma unroll
    for (int mt = 0; mt < 2; mt++)
        aidx[mt] = (((size_t)((off + m0 + wm + mt * 16) >> 4) * KT) * 32 + lane) * 4;
    size_t bidx[8];
    #pragma unroll
    for (int j = 0; j < 8; j++)
        bidx[j] = ((((size_t)e * NB + ((n0 + wn) >> 3) + j) * KT) * 32 + lane) * 2;

    float acc[2][8][4];
    #pragma unroll
    for (int i = 0; i < 2; i++)
        #pragma unroll
        for (int j = 0; j < 8; j++)
            #pragma unroll
            for (int k = 0; k < 4; k++) acc[i][j][k] = 0.f;

    for (int kblk = 0; kblk < KT; kblk++) {
        uint4 ah[2], al[2];
        #pragma unroll
        for (int mt = 0; mt < 2; mt++) {
            ah[mt] = *reinterpret_cast<const uint4*>(AH + aidx[mt]);
            al[mt] = *reinterpret_cast<const uint4*>(AL + aidx[mt]);
            aidx[mt] += 128;
        }
        uint2 bh[8], bl[8];
        #pragma unroll
        for (int j = 0; j < 8; j++) {
            bh[j] = *reinterpret_cast<const uint2*>(WH + bidx[j]);
            bl[j] = *reinterpret_cast<const uint2*>(WL + bidx[j]);
            bidx[j] += 64;
        }
        #pragma unroll
        for (int mt = 0; mt < 2; mt++)
            #pragma unroll
            for (int j = 0; j < 8; j++) {
                MMA_BF16(acc[mt][j], ah[mt].x, ah[mt].y, ah[mt].z, ah[mt].w, bh[j].x, bh[j].y);
                MMA_BF16(acc[mt][j], ah[mt].x, ah[mt].y, ah[mt].z, ah[mt].w, bl[j].x, bl[j].y);
                MMA_BF16(acc[mt][j], al[mt].x, al[mt].y, al[mt].z, al[mt].w, bh[j].x, bh[j].y);
            }
    }

    // ---- epilogue ----
    if (LAYER < 3) {
        uint32_t* __restrict__ OH = (LAYER == 1) ? g_afh1_hi : g_afh2_hi;
        uint32_t* __restrict__ OL = (LAYER == 1) ? g_afh1_lo : g_afh2_lo;
        #pragma unroll
        for (int mt = 0; mt < 2; mt++) {
            const size_t mblk_g = (size_t)((off + m0 + wm + mt * 16) >> 4);
            #pragma unroll
            for (int jp = 0; jp < 4; jp++) {
                const int cb0 = n0 + wn + jp * 16 + 2 * t4;
                const int cb1 = cb0 + 8;
                float b00 = bstack[(size_t)e * NDIM + cb0];
                float b01 = bstack[(size_t)e * NDIM + cb0 + 1];
                float b10 = bstack[(size_t)e * NDIM + cb1];
                float b11 = bstack[(size_t)e * NDIM + cb1 + 1];
                uint32_t hi[4], lo[4];
                split2(fmaxf(acc[mt][2*jp][0]   + b00, 0.f), fmaxf(acc[mt][2*jp][1]   + b01, 0.f), hi[0], lo[0]);
                split2(fmaxf(acc[mt][2*jp][2]   + b00, 0.f), fmaxf(acc[mt][2*jp][3]   + b01, 0.f), hi[1], lo[1]);
                split2(fmaxf(acc[mt][2*jp+1][0] + b10, 0.f), fmaxf(acc[mt][2*jp+1][1] + b11, 0.f), hi[2], lo[2]);
                split2(fmaxf(acc[mt][2*jp+1][2] + b10, 0.f), fmaxf(acc[mt][2*jp+1][3] + b11, 0.f), hi[3], lo[3]);
                const int kblk_n = (n0 + wn) / 16 + jp;
                size_t widx = ((mblk_g * KTn + kblk_n) * 32 + lane) * 4;
                *reinterpret_cast<uint4*>(&OH[widx]) = make_uint4(hi[0], hi[1], hi[2], hi[3]);
                *reinterpret_cast<uint4*>(&OL[widx]) = make_uint4(lo[0], lo[1], lo[2], lo[3]);
            }
        }
    } else {
        #pragma unroll
        for (int mt = 0; mt < 2; mt++) {
            const int r0 = m0 + wm + mt * 16 + g;
            const int r1 = r0 + 8;
            #pragma unroll
            for (int j = 0; j < 8; j++) {
                const int col = n0 + wn + j * 8 + 2 * t4;
                float b0v = bstack[(size_t)e * NDIM + col];
                float b1v = bstack[(size_t)e * NDIM + col + 1];
                if (r0 < cnt) {
                    float2 st; st.x = acc[mt][j][0] + b0v; st.y = acc[mt][j][1] + b1v;
                    *reinterpret_cast<float2*>(&g_o_pair[(size_t)(off + r0) * D_OUT_ + col]) = st;
                }
                if (r1 < cnt) {
                    float2 st; st.x = acc[mt][j][2] + b0v; st.y = acc[mt][j][3] + b1v;
                    *reinterpret_cast<float2*>(&g_o_pair[(size_t)(off + r1) * D_OUT_ + col]) = st;
                }
            }
        }
    }
}

// ==================== parallel per-layer verify ====================
template<int L>
__global__ __launch_bounds__(256)
void verify_layer(const float* __restrict__ x,
                  const float* __restrict__ W, const float* __restrict__ b)
{
    constexpr int KD = (L == 1) ? D_IN_ : D_HID_;
    constexpr int ND = (L == 3) ? D_OUT_ : D_HID_;
    __shared__ float red[256];
    __shared__ int s_bad;
    const int tid = threadIdx.x;
    if (tid == 0) s_bad = 0;
    __syncthreads();

    if (g_mma_ok == 0) { if (tid == 0) g_badL[L - 1] = 1; return; }

    const int r  = (blockIdx.x >= 8) ? 101 : 0;
    const int cg = blockIdx.x & 7;

    int e = -1;
    for (int i = 0; i < E_; i++)
        if (g_offsets[i] <= r && r < g_offsets[i] + g_counts[i]) e = i;
    if (e < 0) return;   // padding row (essentially impossible); treat as pass

    const int col = cg * 32 + (tid & 31);
    const int seg = tid >> 5;
    const int klo = seg * (KD / 8), khi = klo + (KD / 8);

    float partial = 0.f;
    if (L == 1) {
        const int tok = g_pair_token[r];
        for (int k = klo; k < khi; k++)
            partial = fmaf(x[(size_t)tok * KD + k], W[((size_t)e * KD + k) * ND + col], partial);
    } else {
        const uint32_t* hh = (L == 2) ? g_afh1_hi : g_afh2_hi;
        const uint32_t* hl = (L == 2) ? g_afh1_lo : g_afh2_lo;
        for (int k = klo; k < khi; k++)
            partial = fmaf(af_read(hh, hl, r, k, KT2), W[((size_t)e * KD + k) * ND + col], partial);
    }
    red[tid] = partial;
    __syncthreads();
    if (seg == 0) {
        float s = b[(size_t)e * ND + col];
        #pragma unroll
        for (int q = 0; q < 8; q++) s += red[(tid & 31) + q * 32];
        if (L < 3) s = fmaxf(s, 0.f);
        float got;
        if (L == 1)      got = af_read(g_afh1_hi, g_afh1_lo, r, col, KT2);
        else if (L == 2) got = af_read(g_afh2_hi, g_afh2_lo, r, col, KT2);
        else             got = g_o_pair[(size_t)r * ND + col];
        if (!(fabsf(got - s) <= 5e-3f * (fabsf(s) + 0.1f))) s_bad = 1;
    }
    __syncthreads();
    if (tid == 0 && s_bad) atomicOr(&g_badL[L - 1], 1);
}

// ==================== fp32 repair GEMM (fragment-layout writers) ============
#define BM 128
#define BN 128
#define BK 8

template<int KDIM, int NDIM, int LAYER>
__global__ __launch_bounds__(256, 2)
void repair_gemm(const float* __restrict__ xptr,
                 const float* __restrict__ Wstack,
                 const float* __restrict__ bstack)
{
    if (g_badL[LAYER - 1] == 0) return;
    constexpr int KTin = KDIM / 16;
    constexpr int KTo  = NDIM / 16;

    const int e   = blockIdx.z;
    const int cnt = g_counts[e];
    const int m0  = blockIdx.y * BM;
    if (m0 >= cnt) return;
    const int off = g_offsets[e];
    const int n0  = blockIdx.x * BN;

    const float* __restrict__ Wb = Wstack + (size_t)e * KDIM * NDIM;

    __shared__ __align__(16) float As[2][BK][BM];
    __shared__ __align__(16) float Bs[2][BK][BN];

    const int tid   = threadIdx.x;
    const int a_row = tid >> 1;
    const int a_kq  = (tid & 1) << 2;
    const int b_k   = tid >> 5;
    const int b_n   = (tid & 31) << 2;

    int m  = m0 + a_row;
    int mm = (m < cnt) ? m : (cnt - 1);
    const int grow = off + mm;

    const float* Axr = (LAYER == 1) ? xptr + (size_t)g_pair_token[grow] * KDIM : nullptr;
    const uint32_t* AiH = (LAYER == 2) ? g_afh1_hi : g_afh2_hi;
    const uint32_t* AiL = (LAYER == 2) ? g_afh1_lo : g_afh2_lo;

    auto loadA = [&](int k) -> float4 {
        if (LAYER == 1) return *reinterpret_cast<const float4*>(Axr + k);
        size_t i0 = af_widx(grow, k, KTin);
        size_t i1 = af_widx(grow, k + 2, KTin);
        uint32_t h0 = AiH[i0], l0 = AiL[i0], h1 = AiH[i1], l1 = AiL[i1];
        float4 r;
        r.x = bfu(h0) + bfu(l0);
        r.y = bfu(h0 >> 16) + bfu(l0 >> 16);
        r.z = bfu(h1) + bfu(l1);
        r.w = bfu(h1 >> 16) + bfu(l1 >> 16);
        return r;
    };

    const int tx = tid & 15;
    const int ty = tid >> 4;

    float acc[8][8];
    #pragma unroll
    for (int i = 0; i < 8; i++)
        #pragma unroll
        for (int j = 0; j < 8; j++) acc[i][j] = 0.f;

    {
        float4 av = loadA(a_kq);
        float4 bv = *reinterpret_cast<const float4*>(Wb + (size_t)b_k * NDIM + n0 + b_n);
        As[0][a_kq + 0][a_row] = av.x;
        As[0][a_kq + 1][a_row] = av.y;
        As[0][a_kq + 2][a_row] = av.z;
        As[0][a_kq + 3][a_row] = av.w;
        *reinterpret_cast<float4*>(&Bs[0][b_k][b_n]) = bv;
    }
    __syncthreads();

    const int ntiles = KDIM / BK;
    for (int t = 0; t < ntiles; ++t) {
        const int cur = t & 1;
        const int nxt = cur ^ 1;
        float4 an, bn;
        if (t + 1 < ntiles) {
            const int k0 = (t + 1) * BK;
            an = loadA(k0 + a_kq);
            bn = *reinterpret_cast<const float4*>(Wb + (size_t)(k0 + b_k) * NDIM + n0 + b_n);
        }
        #pragma unroll
        for (int kk = 0; kk < BK; kk++) {
            float ar[8], br[8];
            *reinterpret_cast<float4*>(&ar[0]) = *reinterpret_cast<const float4*>(&As[cur][kk][ty * 8]);
            *reinterpret_cast<float4*>(&ar[4]) = *reinterpret_cast<const float4*>(&As[cur][kk][ty * 8 + 4]);
            *reinterpret_cast<float4*>(&br[0]) = *reinterpret_cast<const float4*>(&Bs[cur][kk][tx * 8]);
            *reinterpret_cast<float4*>(&br[4]) = *reinterpret_cast<const float4*>(&Bs[cur][kk][tx * 8 + 4]);
            #pragma unroll
            for (int i = 0; i < 8; i++)
                #pragma unroll
                for (int j = 0; j < 8; j++)
                    acc[i][j] = fmaf(ar[i], br[j], acc[i][j]);
        }
        if (t + 1 < ntiles) {
            As[nxt][a_kq + 0][a_row] = an.x;
            As[nxt][a_kq + 1][a_row] = an.y;
            As[nxt][a_kq + 2][a_row] = an.z;
            As[nxt][a_kq + 3][a_row] = an.w;
            *reinterpret_cast<float4*>(&Bs[nxt][b_k][b_n]) = bn;
        }
        __syncthreads();
    }

    const int col0 = n0 + tx * 8;
    float bias[8];
    #pragma unroll
    for (int j = 0; j < 8; j++) bias[j] = bstack[(size_t)e * NDIM + col0 + j];

    uint32_t* OH = (LAYER == 1) ? g_afh1_hi : g_afh2_hi;
    uint32_t* OL = (LAYER == 1) ? g_afh1_lo : g_afh2_lo;

    #pragma unroll
    for (int i = 0; i < 8; i++) {
        int mr = m0 + ty * 8 + i;
        if (mr >= cnt) continue;
        const int prow = off + mr;
        if (LAYER < 3) {
            #pragma unroll
            for (int jp = 0; jp < 4; jp++) {
                float v0 = fmaxf(acc[i][jp * 2 + 0] + bias[jp * 2 + 0], 0.f);
                float v1 = fmaxf(acc[i][jp * 2 + 1] + bias[jp * 2 + 1], 0.f);
                uint32_t hi, lo;
                split2(v0, v1, hi, lo);
                size_t wi = af_widx(prow, col0 + jp * 2, KTo);
                OH[wi] = hi;
                OL[wi] = lo;
            }
        } else {
            float* orow = g_o_pair + (size_t)prow * D_OUT_ + col0;
            #pragma unroll
            for (int j = 0; j < 8; j++)
                orow[j] = acc[i][j] + bias[j];
        }
    }
}

// ==================== diagnostic spin (small) ====================
__device__ __forceinline__ unsigned long long gtimer() {
    unsigned long long t;
    asm volatile("mov.u64 %0, %%globaltimer;" : "=l"(t));
    return t;
}
__global__ void spin_kernel() {
    if (threadIdx.x != 0) return;
    unsigned long long add = 0;
    if (g_mma_ok == 0) add += 8000000ULL;
    if (g_badL[0]) add += 600000ULL;
    if (g_badL[1]) add += 1200000ULL;
    if (g_badL[2]) add += 2400000ULL;
    if (add) {
        unsigned long long t0 = gtimer();
        while (gtimer() - t0 < add) {}
    }
}

// ==================== combine + finalize ====================
__global__ __launch_bounds__(256)
void combine_kernel(float* __restrict__ out)
{
    int i = blockIdx.x * 256 + threadIdx.x;
    int tok = i >> 10, c = i & 1023;
    float v = g_tok_s[tok * 2 + 0] * g_o_pair[(size_t)g_tok_pos[tok * 2 + 0] * D_OUT_ + c]
            + g_tok_s[tok * 2 + 1] * g_o_pair[(size_t)g_tok_pos[tok * 2 + 1] * D_OUT_ + c];
    out[i] = v;
}

__global__ __launch_bounds__(1024)
void finalize_kernel(float* __restrict__ out, long long out_sz)
{
    __shared__ float red[1024];
    const int tid = threadIdx.x;
    float s = 0.f;
    for (int i = tid; i < B_; i += 1024) s += g_entropy[i];
    red[tid] = s;
    __syncthreads();
    for (int st = 512; st > 0; st >>= 1) {
        if (tid < st) red[tid] += red[tid + st];
        __syncthreads();
    }
    if (tid == 0) {
        float ent_mean = red[0] / (float)B_;
        float load[E_];
        float mean = 0.f;
        for (int e = 0; e < E_; e++) {
            load[e] = (float)g_counts[e] / ((float)B_ + 1e-9f);
            mean += load[e];
        }
        mean /= (float)E_;
        float var = 0.f;
        for (int e = 0; e < E_; e++) {
            float d = load[e] - mean;
            var += d * d;
        }
        var /= (float)(E_ - 1);
        float aux = 5.0f * var + 0.1f * ent_mean;
        long long aux_off = (long long)B_ * D_OUT_;
        if (out_sz > aux_off) out[aux_off] = aux;
    }
}

// ==================== launch ====================
extern "C" void kernel_launch(void* const* d_in, const int* in_sizes, int n_in,
                              void* d_out, int out_size)
{
    const float* x   = (const float*)d_in[0];
    const float* We1 = (const float*)d_in[1];
    const float* be1 = (const float*)d_in[2];
    const float* We2 = (const float*)d_in[3];
    const float* be2 = (const float*)d_in[4];
    const float* We3 = (const float*)d_in[5];
    const float* be3 = (const float*)d_in[6];
    const float* Wg1 = (const float*)d_in[7];
    const float* bg1 = (const float*)d_in[8];
    const float* Wg2 = (const float*)d_in[9];
    const float* bg2 = (const float*)d_in[10];
    const float* Wg3 = (const float*)d_in[11];
    const float* bg3 = (const float*)d_in[12];
    float* out = (float*)d_out;
    long long out_sz = (long long)out_size;

    init_kernel<<<(PAIR_CAP + 255) / 256, 256>>>();
    gate_kernel<<<B_ / 8, 128>>>(x, Wg1, bg1, Wg2, bg2, Wg3, bg3, out, out_sz);
    offsets_kernel<<<1, 32>>>();
    scatter_kernel<<<(B_ + 255) / 256, 256>>>();

    prep_af1<<<(MBT * KT1 * 32 + 255) / 256, 256>>>(x);
    prep_wf<<<(E_ * NB12 * KT1 * 32 + 255) / 256, 256>>>(We1, g_wf1_hi, g_wf1_lo, D_IN_,  D_HID_);
    prep_wf<<<(E_ * NB12 * KT2 * 32 + 255) / 256, 256>>>(We2, g_wf2_hi, g_wf2_lo, D_HID_, D_HID_);
    prep_wf<<<(E_ * NB3  * KT2 * 32 + 255) / 256, 256>>>(We3, g_wf3_hi, g_wf3_lo, D_HID_, D_OUT_);

    mma_selftest<<<1, 32>>>();

    moe_gemm<D_IN_,  D_HID_, 1><<<dim3(64, D_HID_ / 256, E_), 256>>>(be1);
    verify_layer<1><<<16, 256>>>(x, We1, be1);
    repair_gemm<D_IN_,  D_HID_, 1><<<dim3(D_HID_ / BN, 32, E_), 256>>>(x, We1, be1);

    moe_gemm<D_HID_, D_HID_, 2><<<dim3(64, D_HID_ / 256, E_), 256>>>(be2);
    verify_layer<2><<<16, 256>>>(x, We2, be2);
    repair_gemm<D_HID_, D_HID_, 2><<<dim3(D_HID_ / BN, 32, E_), 256>>>(x, We2, be2);

    moe_gemm<D_HID_, D_OUT_, 3><<<dim3(64, D_OUT_ / 256, E_), 256>>>(be3);
    verify_layer<3><<<16, 256>>>(x, We3, be3);
    repair_gemm<D_HID_, D_OUT_, 3><<<dim3(D_OUT_ / BN, 32, E_), 256>>>(x, We3, be3);

    spin_kernel<<<1, 32>>>();

    combine_kernel<<<(B_ * D_OUT_) / 256, 256>>>(out);
    finalize_kernel<<<1, 1024>>>(out, out_sz);
}

// round 10
// speedup vs baseline: 11.3015x; 4.0671x over previous
#include <cuda_runtime.h>
#include <cuda_bf16.h>
#include <math.h>
#include <stdint.h>

#define E_     8
#define B_     4096
#define D_IN_  1024
#define D_HID_ 2048
#define D_OUT_ 1024
#define G_HID_ 128
#define K_     2

// ==================== f32x2 helpers ====================
__device__ __forceinline__ unsigned long long packf2(float lo, float hi) {
    unsigned long long r;
    asm("mov.b64 %0, {%1, %2};" : "=l"(r) : "f"(lo), "f"(hi));
    return r;
}
__device__ __forceinline__ void unpackf2(unsigned long long v, float& lo, float& hi) {
    asm("mov.b64 {%0, %1}, %2;" : "=f"(lo), "=f"(hi) : "l"(v));
}
#define FMA2(acc, a, b) \
    asm("fma.rn.f32x2 %0, %1, %2, %0;" : "+l"(acc) : "l"(a), "l"(b))

// ==================== device scratch ====================
__device__ int   g_counts[E_];
__device__ int   g_offsets[E_];
__device__ int   g_cursor[E_];
__device__ int   g_tok_e[B_ * K_];
__device__ float g_tok_s[B_ * K_];
__device__ int   g_tok_pos[B_ * K_];
__device__ int   g_pair_token[B_ * K_];
__device__ float g_entropy[B_];
__device__ int   g_f2ok;

__device__ __align__(16) float g_f1[(size_t)B_ * K_ * D_HID_];
__device__ __align__(16) float g_f2[(size_t)B_ * K_ * D_HID_];
__device__ __align__(16) float g_o_pair[(size_t)B_ * K_ * D_OUT_];

// ==================== small kernels ====================
__global__ void init_kernel() {
    if (threadIdx.x < E_) { g_counts[threadIdx.x] = 0; g_cursor[threadIdx.x] = 0; }
    if (threadIdx.x == 0) g_f2ok = 0;
}

__global__ void f32x2_selftest() {
    if (threadIdx.x == 0) {
        unsigned long long a = packf2(3.0f, 4.0f);
        unsigned long long b = packf2(5.0f, 6.0f);
        unsigned long long d = packf2(7.0f, 8.0f);
        FMA2(d, a, b);
        float lo, hi;
        unpackf2(d, lo, hi);
        g_f2ok = (lo == 22.0f && hi == 32.0f) ? 1 : 0;
    }
}

__global__ __launch_bounds__(128)
void gate_kernel(const float* __restrict__ x,
                 const float* __restrict__ Wg1, const float* __restrict__ bg1,
                 const float* __restrict__ Wg2, const float* __restrict__ bg2,
                 const float* __restrict__ Wg3, const float* __restrict__ bg3,
                 float* __restrict__ out, long long out_sz)
{
    __shared__ __align__(16) float xs[8][D_IN_];
    __shared__ float s_g1[8][G_HID_];
    __shared__ float s_g2[8][G_HID_];
    __shared__ float s_lg[8][E_];

    const int tid = threadIdx.x;
    const int t0  = blockIdx.x * 8;

    const float4* xg  = reinterpret_cast<const float4*>(x + (size_t)t0 * D_IN_);
    float4*       xsv = reinterpret_cast<float4*>(&xs[0][0]);
    #pragma unroll
    for (int i = 0; i < (8 * D_IN_ / 4) / 128; i++)
        xsv[tid + i * 128] = xg[tid + i * 128];
    __syncthreads();

    float acc[8];
    #pragma unroll
    for (int t = 0; t < 8; t++) acc[t] = 0.f;
    for (int i = 0; i < D_IN_; i++) {
        float w = Wg1[i * G_HID_ + tid];
        #pragma unroll
        for (int t = 0; t < 8; t++) acc[t] = fmaf(xs[t][i], w, acc[t]);
    }
    {
        float b = bg1[tid];
        #pragma unroll
        for (int t = 0; t < 8; t++) s_g1[t][tid] = fmaxf(acc[t] + b, 0.f);
    }
    __syncthreads();

    #pragma unroll
    for (int t = 0; t < 8; t++) acc[t] = 0.f;
    for (int i = 0; i < G_HID_; i++) {
        float w = Wg2[i * G_HID_ + tid];
        #pragma unroll
        for (int t = 0; t < 8; t++) acc[t] = fmaf(s_g1[t][i], w, acc[t]);
    }
    {
        float b = bg2[tid];
        #pragma unroll
        for (int t = 0; t < 8; t++) s_g2[t][tid] = fmaxf(acc[t] + b, 0.f);
    }
    __syncthreads();

    if (tid < 64) {
        int t = tid >> 3, e = tid & 7;
        float a = bg3[e];
        for (int i = 0; i < G_HID_; i++)
            a = fmaf(s_g2[t][i], Wg3[i * E_ + e], a);
        s_lg[t][e] = a;
    }
    __syncthreads();

    if (tid < 8) {
        const int t   = tid;
        const int tok = t0 + t;
        float p[E_];
        float mx = s_lg[t][0];
        #pragma unroll
        for (int e = 1; e < E_; e++) mx = fmaxf(mx, s_lg[t][e]);
        float s = 0.f;
        #pragma unroll
        for (int e = 0; e < E_; e++) { p[e] = expf(s_lg[t][e] - mx); s += p[e]; }
        float inv = 1.f / s;
        float ent = 0.f;
        #pragma unroll
        for (int e = 0; e < E_; e++) { p[e] *= inv; ent -= p[e] * logf(p[e] + 1e-9f); }
        g_entropy[tok] = ent;

        int i1 = 0;
        #pragma unroll
        for (int e = 1; e < E_; e++) if (p[e] > p[i1]) i1 = e;
        int i2 = (i1 == 0) ? 1 : 0;
        #pragma unroll
        for (int e = 0; e < E_; e++) if (e != i1 && p[e] > p[i2]) i2 = e;

        float s1 = p[i1], s2 = p[i2];
        atomicAdd(&g_counts[i1], 1);
        atomicAdd(&g_counts[i2], 1);
        float denom = s1 + s2 + 1e-9f;
        g_tok_e[tok * 2 + 0] = i1;
        g_tok_e[tok * 2 + 1] = i2;
        g_tok_s[tok * 2 + 0] = s1 / denom;
        g_tok_s[tok * 2 + 1] = s2 / denom;

        long long idx_off = (long long)B_ * D_OUT_ + 1;
        long long sc_off  = idx_off + (long long)B_ * K_;
        if (out_sz >= sc_off + (long long)B_ * K_) {
            out[idx_off + tok * 2 + 0] = (float)i1;
            out[idx_off + tok * 2 + 1] = (float)i2;
            out[sc_off  + tok * 2 + 0] = s1;
            out[sc_off  + tok * 2 + 1] = s2;
        }
    }
}

__global__ void offsets_kernel() {
    if (threadIdx.x == 0 && blockIdx.x == 0) {
        int off = 0;
        for (int e = 0; e < E_; e++) {
            g_offsets[e] = off;
            g_cursor[e]  = off;
            off += g_counts[e];
        }
    }
}

__global__ void scatter_kernel() {
    int tok = blockIdx.x * blockDim.x + threadIdx.x;
    if (tok >= B_) return;
    #pragma unroll
    for (int k = 0; k < K_; k++) {
        int e = g_tok_e[tok * 2 + k];
        int pos = atomicAdd(&g_cursor[e], 1);
        g_pair_token[pos] = tok;
        g_tok_pos[tok * 2 + k] = pos;
    }
}

// ==================== shared GEMM tiling ====================
#define BM 128
#define BN 128
#define BK 8

// ============ f32x2 packed GEMM (gated on g_f2ok == 1) ============
// 256 threads; thread (tx=tid&15, ty=tid>>4): rows ty*8+[0,8), cols tx+16j (j=0..7).
template<int KDIM, int NDIM, int EPI, int ASRC>
__global__ __launch_bounds__(256)
void moe_gemm2(const float* __restrict__ xptr,
               const float* __restrict__ Wstack,
               const float* __restrict__ bstack)
{
    if (g_f2ok == 0) return;

    const int e   = blockIdx.z;
    const int cnt = g_counts[e];
    const int m0  = blockIdx.y * BM;
    if (m0 >= cnt) return;
    const int off = g_offsets[e];
    const int n0  = blockIdx.x * BN;

    const float* __restrict__ Wb = Wstack + (size_t)e * KDIM * NDIM;
    const float* __restrict__ Abase =
        (ASRC == 0) ? xptr : (ASRC == 1 ? (const float*)g_f1 : (const float*)g_f2);
    float* __restrict__ Obase =
        (EPI == 0) ? (ASRC == 0 ? (float*)g_f1 : (float*)g_f2) : (float*)g_o_pair;

    __shared__ __align__(16) float As[2][BK][BM];
    __shared__ __align__(16) float Bs[2][BK][BN];

    const int tid   = threadIdx.x;
    const int a_row = tid >> 1;
    const int a_kq  = (tid & 1) << 2;
    const int b_k   = tid >> 5;
    const int b_n   = (tid & 31) << 2;

    int m  = m0 + a_row;
    int mm = (m < cnt) ? m : (cnt - 1);
    const float* __restrict__ Arow =
        (ASRC == 0) ? Abase + (size_t)g_pair_token[off + mm] * KDIM
                    : Abase + (size_t)(off + mm) * KDIM;

    const int tx = tid & 15;
    const int ty = tid >> 4;

    unsigned long long acc2[8][4];
    #pragma unroll
    for (int i = 0; i < 8; i++)
        #pragma unroll
        for (int p = 0; p < 4; p++) acc2[i][p] = 0ULL;

    // prologue: tile 0
    {
        float4 av = *reinterpret_cast<const float4*>(Arow + a_kq);
        float4 bv = *reinterpret_cast<const float4*>(Wb + (size_t)b_k * NDIM + n0 + b_n);
        As[0][a_kq + 0][a_row] = av.x;
        As[0][a_kq + 1][a_row] = av.y;
        As[0][a_kq + 2][a_row] = av.z;
        As[0][a_kq + 3][a_row] = av.w;
        *reinterpret_cast<float4*>(&Bs[0][b_k][b_n]) = bv;
    }
    __syncthreads();

    const int ntiles = KDIM / BK;
    for (int t = 0; t < ntiles; ++t) {
        const int cur = t & 1;
        const int nxt = cur ^ 1;
        float4 an, bn;
        if (t + 1 < ntiles) {
            const int k0 = (t + 1) * BK;
            an = *reinterpret_cast<const float4*>(Arow + k0 + a_kq);
            bn = *reinterpret_cast<const float4*>(Wb + (size_t)(k0 + b_k) * NDIM + n0 + b_n);
        }
        #pragma unroll
        for (int kk = 0; kk < BK; kk++) {
            float ar[8];
            *reinterpret_cast<float4*>(&ar[0]) = *reinterpret_cast<const float4*>(&As[cur][kk][ty * 8]);
            *reinterpret_cast<float4*>(&ar[4]) = *reinterpret_cast<const float4*>(&As[cur][kk][ty * 8 + 4]);
            unsigned long long brp[4];
            #pragma unroll
            for (int p = 0; p < 4; p++)
                brp[p] = packf2(Bs[cur][kk][tx + 32 * p], Bs[cur][kk][tx + 32 * p + 16]);
            #pragma unroll
            for (int i = 0; i < 8; i++) {
                unsigned long long arr = packf2(ar[i], ar[i]);
                #pragma unroll
                for (int p = 0; p < 4; p++)
                    FMA2(acc2[i][p], arr, brp[p]);
            }
        }
        if (t + 1 < ntiles) {
            As[nxt][a_kq + 0][a_row] = an.x;
            As[nxt][a_kq + 1][a_row] = an.y;
            As[nxt][a_kq + 2][a_row] = an.z;
            As[nxt][a_kq + 3][a_row] = an.w;
            *reinterpret_cast<float4*>(&Bs[nxt][b_k][b_n]) = bn;
        }
        __syncthreads();
    }

    // epilogue: cols n0 + tx + 32p (+16)
    float bias0[4], bias1[4];
    #pragma unroll
    for (int p = 0; p < 4; p++) {
        bias0[p] = bstack[(size_t)e * NDIM + n0 + tx + 32 * p];
        bias1[p] = bstack[(size_t)e * NDIM + n0 + tx + 32 * p + 16];
    }
    #pragma unroll
    for (int i = 0; i < 8; i++) {
        int mr = m0 + ty * 8 + i;
        if (mr >= cnt) continue;
        float* orow = Obase + (size_t)(off + mr) * NDIM + n0 + tx;
        #pragma unroll
        for (int p = 0; p < 4; p++) {
            float lo, hi;
            unpackf2(acc2[i][p], lo, hi);
            float v0 = lo + bias0[p];
            float v1 = hi + bias1[p];
            if (EPI == 0) { v0 = fmaxf(v0, 0.f); v1 = fmaxf(v1, 0.f); }
            orow[32 * p]      = v0;
            orow[32 * p + 16] = v1;
        }
    }
}

// ============ scalar fp32 GEMM (round-1 proven; gated on g_f2ok == 0) ============
template<int KDIM, int NDIM, int EPI, int ASRC>
__global__ __launch_bounds__(256, 2)
void fb_gemm(const float* __restrict__ xptr,
             const float* __restrict__ Wstack,
             const float* __restrict__ bstack)
{
    if (g_f2ok != 0) return;

    const int e   = blockIdx.z;
    const int cnt = g_counts[e];
    const int m0  = blockIdx.y * BM;
    if (m0 >= cnt) return;
    const int off = g_offsets[e];
    const int n0  = blockIdx.x * BN;

    const float* __restrict__ Wb = Wstack + (size_t)e * KDIM * NDIM;
    const float* __restrict__ Abase =
        (ASRC == 0) ? xptr : (ASRC == 1 ? (const float*)g_f1 : (const float*)g_f2);
    float* __restrict__ Obase =
        (EPI == 0) ? (ASRC == 0 ? (float*)g_f1 : (float*)g_f2) : (float*)g_o_pair;

    __shared__ __align__(16) float As[2][BK][BM];
    __shared__ __align__(16) float Bs[2][BK][BN];

    const int tid   = threadIdx.x;
    const int a_row = tid >> 1;
    const int a_kq  = (tid & 1) << 2;
    const int b_k   = tid >> 5;
    const int b_n   = (tid & 31) << 2;

    int m  = m0 + a_row;
    int mm = (m < cnt) ? m : (cnt - 1);
    const float* __restrict__ Arow =
        (ASRC == 0) ? Abase + (size_t)g_pair_token[off + mm] * KDIM
                    : Abase + (size_t)(off + mm) * KDIM;

    const int tx = tid & 15;
    const int ty = tid >> 4;

    float acc[8][8];
    #pragma unroll
    for (int i = 0; i < 8; i++)
        #pragma unroll
        for (int j = 0; j < 8; j++) acc[i][j] = 0.f;

    {
        float4 av = *reinterpret_cast<const float4*>(Arow + a_kq);
        float4 bv = *reinterpret_cast<const float4*>(Wb + (size_t)b_k * NDIM + n0 + b_n);
        As[0][a_kq + 0][a_row] = av.x;
        As[0][a_kq + 1][a_row] = av.y;
        As[0][a_kq + 2][a_row] = av.z;
        As[0][a_kq + 3][a_row] = av.w;
        *reinterpret_cast<float4*>(&Bs[0][b_k][b_n]) = bv;
    }
    __syncthreads();

    const int ntiles = KDIM / BK;
    for (int t = 0; t < ntiles; ++t) {
        const int cur = t & 1;
        const int nxt = cur ^ 1;
        float4 an, bn;
        if (t + 1 < ntiles) {
            const int k0 = (t + 1) * BK;
            an = *reinterpret_cast<const float4*>(Arow + k0 + a_kq);
            bn = *reinterpret_cast<const float4*>(Wb + (size_t)(k0 + b_k) * NDIM + n0 + b_n);
        }
        #pragma unroll
        for (int kk = 0; kk < BK; kk++) {
            float ar[8], br[8];
            *reinterpret_cast<float4*>(&ar[0]) = *reinterpret_cast<const float4*>(&As[cur][kk][ty * 8]);
            *reinterpret_cast<float4*>(&ar[4]) = *reinterpret_cast<const float4*>(&As[cur][kk][ty * 8 + 4]);
            *reinterpret_cast<float4*>(&br[0]) = *reinterpret_cast<const float4*>(&Bs[cur][kk][tx * 8]);
            *reinterpret_cast<float4*>(&br[4]) = *reinterpret_cast<const float4*>(&Bs[cur][kk][tx * 8 + 4]);
            #pragma unroll
            for (int i = 0; i < 8; i++)
                #pragma unroll
                for (int j = 0; j < 8; j++)
                    acc[i][j] = fmaf(ar[i], br[j], acc[i][j]);
        }
        if (t + 1 < ntiles) {
            As[nxt][a_kq + 0][a_row] = an.x;
            As[nxt][a_kq + 1][a_row] = an.y;
            As[nxt][a_kq + 2][a_row] = an.z;
            As[nxt][a_kq + 3][a_row] = an.w;
            *reinterpret_cast<float4*>(&Bs[nxt][b_k][b_n]) = bn;
        }
        __syncthreads();
    }

    const int col0 = n0 + tx * 8;
    float bias[8];
    #pragma unroll
    for (int j = 0; j < 8; j++) bias[j] = bstack[(size_t)e * NDIM + col0 + j];

    #pragma unroll
    for (int i = 0; i < 8; i++) {
        int mr = m0 + ty * 8 + i;
        if (mr >= cnt) continue;
        float* orow = Obase + (size_t)(off + mr) * NDIM + col0;
        #pragma unroll
        for (int j = 0; j < 8; j++) {
            float v = acc[i][j] + bias[j];
            orow[j] = (EPI == 0) ? fmaxf(v, 0.f) : v;
        }
    }
}

// ==================== combine + finalize ====================
__global__ __launch_bounds__(256)
void combine_kernel(float* __restrict__ out)
{
    int i = blockIdx.x * 256 + threadIdx.x;
    int tok = i >> 10, c = i & 1023;
    float v = g_tok_s[tok * 2 + 0] * g_o_pair[(size_t)g_tok_pos[tok * 2 + 0] * D_OUT_ + c]
            + g_tok_s[tok * 2 + 1] * g_o_pair[(size_t)g_tok_pos[tok * 2 + 1] * D_OUT_ + c];
    out[i] = v;
}

__global__ __launch_bounds__(1024)
void finalize_kernel(float* __restrict__ out, long long out_sz)
{
    __shared__ float red[1024];
    const int tid = threadIdx.x;
    float s = 0.f;
    for (int i = tid; i < B_; i += 1024) s += g_entropy[i];
    red[tid] = s;
    __syncthreads();
    for (int st = 512; st > 0; st >>= 1) {
        if (tid < st) red[tid] += red[tid + st];
        __syncthreads();
    }
    if (tid == 0) {
        float ent_mean = red[0] / (float)B_;
        float load[E_];
        float mean = 0.f;
        for (int e = 0; e < E_; e++) {
            load[e] = (float)g_counts[e] / ((float)B_ + 1e-9f);
            mean += load[e];
        }
        mean /= (float)E_;
        float var = 0.f;
        for (int e = 0; e < E_; e++) {
            float d = load[e] - mean;
            var += d * d;
        }
        var /= (float)(E_ - 1);
        float aux = 5.0f * var + 0.1f * ent_mean;
        long long aux_off = (long long)B_ * D_OUT_;
        if (out_sz > aux_off) out[aux_off] = aux;
    }
}

// ==================== launch ====================
extern "C" void kernel_launch(void* const* d_in, const int* in_sizes, int n_in,
                              void* d_out, int out_size)
{
    const float* x   = (const float*)d_in[0];
    const float* We1 = (const float*)d_in[1];
    const float* be1 = (const float*)d_in[2];
    const float* We2 = (const float*)d_in[3];
    const float* be2 = (const float*)d_in[4];
    const float* We3 = (const float*)d_in[5];
    const float* be3 = (const float*)d_in[6];
    const float* Wg1 = (const float*)d_in[7];
    const float* bg1 = (const float*)d_in[8];
    const float* Wg2 = (const float*)d_in[9];
    const float* bg2 = (const float*)d_in[10];
    const float* Wg3 = (const float*)d_in[11];
    const float* bg3 = (const float*)d_in[12];
    float* out = (float*)d_out;
    long long out_sz = (long long)out_size;

    init_kernel<<<1, 32>>>();
    gate_kernel<<<B_ / 8, 128>>>(x, Wg1, bg1, Wg2, bg2, Wg3, bg3, out, out_sz);
    offsets_kernel<<<1, 32>>>();
    scatter_kernel<<<(B_ + 255) / 256, 256>>>();
    f32x2_selftest<<<1, 32>>>();

    const int max_mt = B_ / 128;   // per-expert cnt <= B
    dim3 g1(D_HID_ / BN, max_mt, E_);
    dim3 g3(D_OUT_ / BN, max_mt, E_);

    moe_gemm2<D_IN_,  D_HID_, 0, 0><<<g1, 256>>>(x, We1, be1);
    fb_gemm  <D_IN_,  D_HID_, 0, 0><<<g1, 256>>>(x, We1, be1);

    moe_gemm2<D_HID_, D_HID_, 0, 1><<<g1, 256>>>(x, We2, be2);
    fb_gemm  <D_HID_, D_HID_, 0, 1><<<g1, 256>>>(x, We2, be2);

    moe_gemm2<D_HID_, D_OUT_, 2, 2><<<g3, 256>>>(x, We3, be3);
    fb_gemm  <D_HID_, D_OUT_, 2, 2><<<g3, 256>>>(x, We3, be3);

    combine_kernel<<<(B_ * D_OUT_) / 256, 256>>>(out);
    finalize_kernel<<<1, 1024>>>(out, out_sz);
}